// round 8
// baseline (speedup 1.0000x reference)
#include <cuda_runtime.h>
#include <cuda_bf16.h>
#include <cuda_fp16.h>
#include <cstdint>

#define N_NODES 100000
#define N_EDGES 1600000
#define IN_DIM 128
#define HID 256
#define EPS 1e-5f

// ======================= scratch (static __device__) =======================
__device__ float g_hraw[N_NODES * HID];                 // GEMM output fp32
__device__ __nv_bfloat16 g_ah[N_NODES * HID];           // aggf16 [N,256] (fp16, reinterpreted) / L0 agg
__device__ __nv_bfloat16 g_al[N_NODES * HID];           // xf16 [N,128] fp16 (reinterpreted)
__device__ __nv_bfloat16 g_bh1[N_NODES * HID];          // L0 agg hi / L2 h_norm hi
__device__ __nv_bfloat16 g_bl1[N_NODES * HID];          // L0 agg lo / L2 h_norm lo
__device__ __nv_bfloat16 g_bh2[N_NODES * HID];          // x hi (bf16)
__device__ __nv_bfloat16 g_bl2[N_NODES * HID];          // x lo (bf16)
__device__ __half g_hf16[N_NODES * HID];                // fp16 h_norm stream (L0/L1 outputs)
__device__ __nv_bfloat16 g_w[720896];                   // bf16 weight pool
__device__ __half g_wf[524288];                         // fp16 weight pool (L1/L2)
__device__ int   g_cnt[N_NODES];
__device__ int   g_cursor[N_NODES];
__device__ int   g_scantmp[N_NODES];
__device__ int   g_rowptr[N_NODES + 1];
__device__ int   g_adj[N_EDGES];
__device__ int   g_bsum[128];
__device__ float g_colsum[3][HID];
__device__ float g_colsumsq[3][HID];

// bf16 pool offsets
#define WL0H 0
#define WL0L 32768
#define WR0H 65536
#define WR0L 98304
#define CW1H 131072
#define CW1L 163840
// fp16 pool offsets
#define WF1LH 0
#define WF1LL 65536
#define WF1RH 131072
#define WF1RL 196608
#define WF2LH 262144
#define WF2LL 327680
#define WF2RH 393216
#define WF2RL 458752

__device__ __forceinline__ uint32_t smem_u32(const void* p) {
    uint32_t a;
    asm("{ .reg .u64 t; cvta.to.shared.u64 t, %1; cvt.u32.u64 %0, t; }" : "=r"(a) : "l"(p));
    return a;
}

// ======================= CSR build =======================
__global__ void k_init() {
    int i = blockIdx.x * blockDim.x + threadIdx.x;
    if (i < N_NODES) { g_cnt[i] = 0; g_cursor[i] = 0; }
    if (i < HID) {
        #pragma unroll
        for (int l = 0; l < 3; l++) { g_colsum[l][i] = 0.f; g_colsumsq[l][i] = 0.f; }
    }
}
__global__ void k_hist(const int* __restrict__ dst) {
    int e = blockIdx.x * blockDim.x + threadIdx.x;
    if (e < N_EDGES) atomicAdd(&g_cnt[dst[e]], 1);
}
__global__ void k_scan1() {
    __shared__ int s[1024];
    int i = blockIdx.x * 1024 + threadIdx.x;
    int v = (i < N_NODES) ? g_cnt[i] : 0;
    s[threadIdx.x] = v;
    __syncthreads();
    #pragma unroll
    for (int off = 1; off < 1024; off <<= 1) {
        int t = (threadIdx.x >= off) ? s[threadIdx.x - off] : 0;
        __syncthreads();
        s[threadIdx.x] += t;
        __syncthreads();
    }
    if (i < N_NODES) g_scantmp[i] = s[threadIdx.x];
    if (threadIdx.x == 1023) g_bsum[blockIdx.x] = s[1023];
}
__global__ void k_scan2(int nb) {
    if (threadIdx.x == 0 && blockIdx.x == 0) {
        int acc = 0;
        for (int i = 0; i < nb; i++) { int v = g_bsum[i]; g_bsum[i] = acc; acc += v; }
    }
}
__global__ void k_scan3() {
    int i = blockIdx.x * 1024 + threadIdx.x;
    if (i < N_NODES) {
        g_rowptr[i + 1] = g_scantmp[i] + g_bsum[blockIdx.x];
        if (i == 0) g_rowptr[0] = 0;
    }
}
__global__ void k_fill(const int* __restrict__ src, const int* __restrict__ dst) {
    int e = blockIdx.x * blockDim.x + threadIdx.x;
    if (e < N_EDGES) {
        int d = dst[e];
        int pos = g_rowptr[d] + atomicAdd(&g_cursor[d], 1);
        g_adj[pos] = src[e];
    }
}

// ======================= pack helpers =======================
__device__ __forceinline__ uint32_t pack2bf(float a, float b) {
    uint16_t ua = __bfloat16_as_ushort(__float2bfloat16(a));
    uint16_t ub = __bfloat16_as_ushort(__float2bfloat16(b));
    return (uint32_t)ua | ((uint32_t)ub << 16);
}
__device__ __forceinline__ float lo_of(float v) {
    return v - __bfloat162float(__float2bfloat16(v));
}

// ======================= aggregation =======================
__global__ void k_agg16_128(const __half* __restrict__ xf,
                            __nv_bfloat16* __restrict__ oh, __nv_bfloat16* __restrict__ ol) {
    int w = (blockIdx.x * blockDim.x + threadIdx.x) >> 5;
    int lane = threadIdx.x & 31;
    if (w >= N_NODES) return;
    int s0 = g_rowptr[w], s1 = g_rowptr[w + 1];
    float a0 = 0.f, a1 = 0.f, a2 = 0.f, a3 = 0.f;
    for (int e = s0; e < s1; e++) {
        uint2 v = *(const uint2*)(xf + (size_t)g_adj[e] * IN_DIM + lane * 4);
        float2 f0 = __half22float2(*(const __half2*)&v.x);
        float2 f1 = __half22float2(*(const __half2*)&v.y);
        a0 += f0.x; a1 += f0.y; a2 += f1.x; a3 += f1.y;
    }
    int deg = s1 - s0;
    float inv = 1.f / (float)(deg > 0 ? deg : 1);
    a0 *= inv; a1 *= inv; a2 *= inv; a3 *= inv;
    size_t base = (size_t)w * IN_DIM + lane * 4;
    uint2 uh, ul;
    uh.x = pack2bf(a0, a1); uh.y = pack2bf(a2, a3);
    ul.x = pack2bf(lo_of(a0), lo_of(a1)); ul.y = pack2bf(lo_of(a2), lo_of(a3));
    *(uint2*)(oh + base) = uh;
    *(uint2*)(ol + base) = ul;
}

__global__ void k_agg16_256(const __half* __restrict__ xf, __half* __restrict__ o16) {
    int w = (blockIdx.x * blockDim.x + threadIdx.x) >> 5;
    int lane = threadIdx.x & 31;
    if (w >= N_NODES) return;
    int s0 = g_rowptr[w], s1 = g_rowptr[w + 1];
    float acc[8];
    #pragma unroll
    for (int i = 0; i < 8; i++) acc[i] = 0.f;
    for (int e = s0; e < s1; e++) {
        size_t base = (size_t)g_adj[e] * HID + lane * 8;
        uint4 v = *(const uint4*)(xf + base);
        const uint32_t* p = &v.x;
        #pragma unroll
        for (int i = 0; i < 4; i++) {
            float2 f = __half22float2(*(const __half2*)&p[i]);
            acc[i * 2 + 0] += f.x;
            acc[i * 2 + 1] += f.y;
        }
    }
    int deg = s1 - s0;
    float inv = 1.f / (float)(deg > 0 ? deg : 1);
    uint4 u;
    uint32_t* p = &u.x;
    #pragma unroll
    for (int i = 0; i < 4; i++) {
        __half2 h = __floats2half2_rn(acc[i * 2] * inv, acc[i * 2 + 1] * inv);
        p[i] = *(uint32_t*)&h;
    }
    *(uint4*)(o16 + (size_t)w * HID + lane * 8) = u;
}

// ======================= conversions =======================
__global__ void k_convx(const float* __restrict__ x,
                        __nv_bfloat16* __restrict__ oh, __nv_bfloat16* __restrict__ ol,
                        __half* __restrict__ o16) {
    int i = blockIdx.x * blockDim.x + threadIdx.x;   // float4 index
    if (i >= N_NODES * IN_DIM / 4) return;
    float4 v = ((const float4*)x)[i];
    uint2 uh, ul, uf;
    uh.x = pack2bf(v.x, v.y); uh.y = pack2bf(v.z, v.w);
    ul.x = pack2bf(lo_of(v.x), lo_of(v.y)); ul.y = pack2bf(lo_of(v.z), lo_of(v.w));
    __half2 f0 = __floats2half2_rn(v.x, v.y);
    __half2 f1 = __floats2half2_rn(v.z, v.w);
    uf.x = *(uint32_t*)&f0; uf.y = *(uint32_t*)&f1;
    ((uint2*)oh)[i] = uh;
    ((uint2*)ol)[i] = ul;
    ((uint2*)o16)[i] = uf;
}

struct ConvJobs { const float* W[7]; int K[7]; int N[7]; int oh[7]; int ol[7]; int mode[7]; };
__global__ void k_convall(ConvJobs j, __nv_bfloat16* __restrict__ wp, __half* __restrict__ wf) {
    int s = blockIdx.y;
    int K = j.K[s], N = j.N[s];
    int id = blockIdx.x * blockDim.x + threadIdx.x;
    if (id >= K * N) return;
    int k = id / N, n = id % N;
    float v = __ldg(&j.W[s][id]);
    size_t pos = (size_t)n * K + k;
    if (j.mode[s] == 0) {
        wp[j.oh[s] + pos] = __float2bfloat16(v);
        wp[j.ol[s] + pos] = __float2bfloat16(lo_of(v));
    } else {
        __half h = __float2half_rn(v);
        wf[j.oh[s] + pos] = h;
        wf[j.ol[s] + pos] = __float2half_rn(v - __half2float(h));
    }
}

// ======================= mma.sync GEMM (bf16 or f16) =======================
// 128 threads, 4 warps in 2x2, warp tile 64x64. BM=128, BN=128, BK=64, 3-stage.
struct GemmSegs { const void* A[6]; const void* W[6]; };

#define MMA_BF16(c, a, b0v, b1v) \
    asm volatile("mma.sync.aligned.m16n8k16.row.col.f32.bf16.bf16.f32 " \
        "{%0,%1,%2,%3}, {%4,%5,%6,%7}, {%8,%9}, {%0,%1,%2,%3};" \
        : "+f"((c)[0]), "+f"((c)[1]), "+f"((c)[2]), "+f"((c)[3]) \
        : "r"((a)[0]), "r"((a)[1]), "r"((a)[2]), "r"((a)[3]), "r"(b0v), "r"(b1v))
#define MMA_F16(c, a, b0v, b1v) \
    asm volatile("mma.sync.aligned.m16n8k16.row.col.f32.f16.f16.f32 " \
        "{%0,%1,%2,%3}, {%4,%5,%6,%7}, {%8,%9}, {%0,%1,%2,%3};" \
        : "+f"((c)[0]), "+f"((c)[1]), "+f"((c)[2]), "+f"((c)[3]) \
        : "r"((a)[0]), "r"((a)[1]), "r"((a)[2]), "r"((a)[3]), "r"(b0v), "r"(b1v))

template <int NT, int STATS, int FINAL, int DT>
__global__ __launch_bounds__(128, 2)
void k_mma(GemmSegs segs, int nseg, int D, const float* __restrict__ bias,
           float* __restrict__ C, int relu,
           const float* __restrict__ w2, const float* __restrict__ b2,
           float* __restrict__ csum, float* __restrict__ cqsum) {
    extern __shared__ char dsm[];                 // 3 stages x [A 16KB | B 16KB]
    __shared__ float scol[128], scolq[128];
    __shared__ float srow[256];
    __shared__ float s_w2[256];
    const uint32_t sb = smem_u32(dsm);
    const int tid = threadIdx.x;
    const int lane = tid & 31, wid = tid >> 5;
    const int wm = wid & 1, wn = wid >> 1;        // 2 m-warps x 2 n-warps, tile 64x64
    const int bm0 = blockIdx.y * 128, bn0 = blockIdx.x * 128;
    const int grp = lane >> 3, tg = lane & 7;

    if (STATS) { scol[tid] = 0.f; scolq[tid] = 0.f; }
    if (FINAL) {
        srow[tid] = 0.f; srow[tid + 128] = 0.f;
        s_w2[tid] = __ldg(&w2[tid]); s_w2[tid + 128] = __ldg(&w2[tid + 128]);
    }

    const int cpsLog = (D == 256) ? 2 : 1;
    const int nkb = nseg << cpsLog;

    const uint32_t xr = (uint32_t)tg << 4;
    const int rowA0 = wm * 64 + tg + (grp & 1) * 8;
    const int rowB0 = wn * 64 + tg + (grp >> 1) * 8;
    const uint32_t kA = (uint32_t)(grp >> 1) * 16;
    const uint32_t kB = (uint32_t)(grp & 1) * 16;

    float acc[4][8][4];
    #pragma unroll
    for (int mt = 0; mt < 4; mt++)
        #pragma unroll
        for (int nt = 0; nt < 8; nt++)
            #pragma unroll
            for (int j = 0; j < 4; j++) acc[mt][nt][j] = 0.f;

    auto load_stage = [&](int kb, int st) {
        int seg = kb >> cpsLog;
        int koff = (kb & ((1 << cpsLog) - 1)) << 6;
        const uint16_t* Aseg = (const uint16_t*)segs.A[seg];
        const uint16_t* Wseg = (const uint16_t*)segs.W[seg];
        uint32_t sA = sb + (uint32_t)st * 32768u;
        uint32_t sB = sA + 16384u;
        #pragma unroll
        for (int t = 0; t < 8; t++) {
            int idx = tid + t * 128;
            int row = idx >> 3, ch = idx & 7;
            uint32_t swz = (uint32_t)row * 128u + (((uint32_t)ch * 16u) ^ (((uint32_t)row & 7u) << 4));
            int grow = bm0 + row;
            int ok = grow < N_NODES;
            const void* gA = Aseg + (size_t)(ok ? grow : 0) * D + koff + ch * 8;
            int sz = ok ? 16 : 0;
            asm volatile("cp.async.cg.shared.global [%0], [%1], 16, %2;"
                         :: "r"(sA + swz), "l"(gA), "r"(sz));
            const void* gB = Wseg + (size_t)(bn0 + row) * D + koff + ch * 8;
            asm volatile("cp.async.cg.shared.global [%0], [%1], 16;"
                         :: "r"(sB + swz), "l"(gB));
        }
        asm volatile("cp.async.commit_group;");
    };

    auto compute_stage = [&](int st) {
        uint32_t aBase = sb + (uint32_t)st * 32768u + (uint32_t)rowA0 * 128u;
        uint32_t bBase = sb + (uint32_t)st * 32768u + 16384u + (uint32_t)rowB0 * 128u;
        #pragma unroll
        for (int kt = 0; kt < 4; kt++) {
            uint32_t a[4][4];
            #pragma unroll
            for (int mt = 0; mt < 4; mt++) {
                uint32_t ad = aBase + (uint32_t)mt * 2048u + (((uint32_t)kt * 32u + kA) ^ xr);
                asm volatile("ldmatrix.sync.aligned.m8n8.x4.shared.b16 {%0,%1,%2,%3}, [%4];"
                    : "=r"(a[mt][0]), "=r"(a[mt][1]), "=r"(a[mt][2]), "=r"(a[mt][3]) : "r"(ad));
            }
            #pragma unroll
            for (int np = 0; np < 4; np++) {
                uint32_t b0, b1, b2r, b3;
                uint32_t bd = bBase + (uint32_t)np * 2048u + (((uint32_t)kt * 32u + kB) ^ xr);
                asm volatile("ldmatrix.sync.aligned.m8n8.x4.shared.b16 {%0,%1,%2,%3}, [%4];"
                    : "=r"(b0), "=r"(b1), "=r"(b2r), "=r"(b3) : "r"(bd));
                #pragma unroll
                for (int mt = 0; mt < 4; mt++) {
                    if (DT == 0) {
                        MMA_BF16(acc[mt][np * 2 + 0], a[mt], b0, b1);
                        MMA_BF16(acc[mt][np * 2 + 1], a[mt], b2r, b3);
                    } else {
                        MMA_F16(acc[mt][np * 2 + 0], a[mt], b0, b1);
                        MMA_F16(acc[mt][np * 2 + 1], a[mt], b2r, b3);
                    }
                }
            }
        }
    };

    load_stage(0, 0);
    load_stage(1, 1);
    int st = 0;
    for (int kb = 0; kb < nkb; kb++) {
        if (kb < nkb - 1) asm volatile("cp.async.wait_group 1;");
        else              asm volatile("cp.async.wait_group 0;");
        __syncthreads();
        compute_stage(st);
        if (kb + 2 < nkb) {
            int st2 = st + 2; if (st2 >= 3) st2 -= 3;
            load_stage(kb + 2, st2);
        }
        if (++st == 3) st = 0;
    }

    // ---- epilogue ----
    const int rbase = wm * 64 + (lane >> 2);
    const int cbL = wn * 64 + (lane & 3) * 2;
    float po[16];
    #pragma unroll
    for (int i = 0; i < 16; i++) po[i] = 0.f;

    #pragma unroll
    for (int nt = 0; nt < 8; nt++) {
        int colL = cbL + nt * 8;
        int col = bn0 + colL;
        float bv0 = __ldg(&bias[col]), bv1 = __ldg(&bias[col + 1]);
        float s0 = 0.f, s1 = 0.f, q0 = 0.f, q1 = 0.f;
        #pragma unroll
        for (int mt = 0; mt < 4; mt++) {
            int row = bm0 + rbase + mt * 16;
            float h0 = acc[mt][nt][0] + bv0, h1 = acc[mt][nt][1] + bv1;
            float h2 = acc[mt][nt][2] + bv0, h3 = acc[mt][nt][3] + bv1;
            if (relu) {
                h0 = fmaxf(h0, 0.f); h1 = fmaxf(h1, 0.f);
                h2 = fmaxf(h2, 0.f); h3 = fmaxf(h3, 0.f);
            }
            bool v0 = row < N_NODES, v1 = (row + 8) < N_NODES;
            if (STATS) {
                float a0 = v0 ? h0 : 0.f, a1 = v0 ? h1 : 0.f;
                float a2 = v1 ? h2 : 0.f, a3 = v1 ? h3 : 0.f;
                s0 += a0 + a2; s1 += a1 + a3;
                q0 += a0 * a0 + a2 * a2; q1 += a1 * a1 + a3 * a3;
            }
            if (!FINAL) {
                if (v0) *(float2*)(C + (size_t)row * NT + col) = make_float2(h0, h1);
                if (v1) *(float2*)(C + (size_t)(row + 8) * NT + col) = make_float2(h2, h3);
            } else {
                float w20 = s_w2[colL * 2], w21 = s_w2[colL * 2 + 1];
                float w30 = s_w2[(colL + 1) * 2], w31 = s_w2[(colL + 1) * 2 + 1];
                po[mt * 4 + 0] += h0 * w20 + h1 * w30;
                po[mt * 4 + 1] += h0 * w21 + h1 * w31;
                po[mt * 4 + 2] += h2 * w20 + h3 * w30;
                po[mt * 4 + 3] += h2 * w21 + h3 * w31;
            }
        }
        if (STATS) {
            #pragma unroll
            for (int off = 4; off <= 16; off <<= 1) {
                s0 += __shfl_xor_sync(0xffffffffu, s0, off);
                s1 += __shfl_xor_sync(0xffffffffu, s1, off);
                q0 += __shfl_xor_sync(0xffffffffu, q0, off);
                q1 += __shfl_xor_sync(0xffffffffu, q1, off);
            }
            if ((lane >> 2) == 0) {
                atomicAdd(&scol[colL], s0);  atomicAdd(&scol[colL + 1], s1);
                atomicAdd(&scolq[colL], q0); atomicAdd(&scolq[colL + 1], q1);
            }
        }
    }
    if (STATS) {
        __syncthreads();
        atomicAdd(&csum[bn0 + tid], scol[tid]);
        atomicAdd(&cqsum[bn0 + tid], scolq[tid]);
    }
    if (FINAL) {
        #pragma unroll
        for (int mt = 0; mt < 4; mt++) {
            int rl = rbase + mt * 16;
            atomicAdd(&srow[rl * 2 + 0], po[mt * 4 + 0]);
            atomicAdd(&srow[rl * 2 + 1], po[mt * 4 + 1]);
            atomicAdd(&srow[(rl + 8) * 2 + 0], po[mt * 4 + 2]);
            atomicAdd(&srow[(rl + 8) * 2 + 1], po[mt * 4 + 3]);
        }
        __syncthreads();
        int grow = bm0 + tid;
        if (grow < N_NODES) {
            C[(size_t)grow * 2 + 0] = srow[tid * 2 + 0] + __ldg(&b2[0]);
            C[(size_t)grow * 2 + 1] = srow[tid * 2 + 1] + __ldg(&b2[1]);
        }
    }
}

// ======== normalize + relu; OUT=0 -> fp16 only; OUT=1 -> bf16 hi/lo only ========
template <int OUT>
__global__ void k_normfuse(const float* __restrict__ h,
                           const float* __restrict__ g, const float* __restrict__ be,
                           const float* __restrict__ csum, const float* __restrict__ cqsum,
                           __nv_bfloat16* __restrict__ oh, __nv_bfloat16* __restrict__ ol,
                           __half* __restrict__ of) {
    __shared__ float sna[HID], snc[HID];
    int tid = threadIdx.x;
    {
        float cs = csum[tid], cq = cqsum[tid];
        float mu  = cs / (float)N_NODES;
        float var = cq / (float)N_NODES - mu * mu;
        var = fmaxf(var, 0.f);
        float a = __ldg(&g[tid]) * rsqrtf(var + EPS);
        sna[tid] = a;
        snc[tid] = __ldg(&be[tid]) - mu * a;
    }
    __syncthreads();
    #pragma unroll
    for (int pass = 0; pass < 4; pass++) {
        int i = blockIdx.x * 1024 + pass * 256 + tid;    // float4 index
        if (i >= N_NODES * HID / 4) return;
        float4 v = ((const float4*)h)[i];
        int cidx = (i * 4) & (HID - 1);
        v.x = fmaxf(v.x * sna[cidx + 0] + snc[cidx + 0], 0.f);
        v.y = fmaxf(v.y * sna[cidx + 1] + snc[cidx + 1], 0.f);
        v.z = fmaxf(v.z * sna[cidx + 2] + snc[cidx + 2], 0.f);
        v.w = fmaxf(v.w * sna[cidx + 3] + snc[cidx + 3], 0.f);
        if (OUT == 0) {
            __half2 f0 = __floats2half2_rn(v.x, v.y);
            __half2 f1 = __floats2half2_rn(v.z, v.w);
            uint2 uf;
            uf.x = *(uint32_t*)&f0; uf.y = *(uint32_t*)&f1;
            ((uint2*)of)[i] = uf;
        } else {
            uint2 uh, ul;
            uh.x = pack2bf(v.x, v.y); uh.y = pack2bf(v.z, v.w);
            ul.x = pack2bf(lo_of(v.x), lo_of(v.y)); ul.y = pack2bf(lo_of(v.z), lo_of(v.w));
            ((uint2*)oh)[i] = uh;
            ((uint2*)ol)[i] = ul;
        }
    }
}

// ======================= launch =======================
extern "C" void kernel_launch(void* const* d_in, const int* in_sizes, int n_in,
                              void* d_out, int out_size) {
    const float* x    = (const float*)d_in[0];
    const int*   ei   = (const int*)d_in[1];   // int32 (JAX x64 disabled)
    const int*   srcv = ei;
    const int*   dstv = ei + N_EDGES;
    const float* wl0 = (const float*)d_in[2];
    const float* wr0 = (const float*)d_in[3];
    const float* b0  = (const float*)d_in[4];
    const float* g0  = (const float*)d_in[5];
    const float* be0 = (const float*)d_in[6];
    const float* wl1 = (const float*)d_in[7];
    const float* wr1 = (const float*)d_in[8];
    const float* b1  = (const float*)d_in[9];
    const float* g1  = (const float*)d_in[10];
    const float* be1 = (const float*)d_in[11];
    const float* wl2 = (const float*)d_in[12];
    const float* wr2 = (const float*)d_in[13];
    const float* b2  = (const float*)d_in[14];
    const float* g2  = (const float*)d_in[15];
    const float* be2 = (const float*)d_in[16];
    const float* cw1 = (const float*)d_in[17];
    const float* cb1 = (const float*)d_in[18];
    const float* cw2 = (const float*)d_in[19];
    const float* cb2 = (const float*)d_in[20];
    float* out = (float*)d_out;

    float* hraw;
    __nv_bfloat16 *aggbuf, *xfbuf, *bh1, *bl1, *bh2, *bl2, *wp;
    __half *hf16, *wf;
    float *cs, *cq;
    cudaGetSymbolAddress((void**)&hraw, g_hraw);
    cudaGetSymbolAddress((void**)&aggbuf, g_ah);
    cudaGetSymbolAddress((void**)&xfbuf, g_al);
    cudaGetSymbolAddress((void**)&bh1, g_bh1);
    cudaGetSymbolAddress((void**)&bl1, g_bl1);
    cudaGetSymbolAddress((void**)&bh2, g_bh2);
    cudaGetSymbolAddress((void**)&bl2, g_bl2);
    cudaGetSymbolAddress((void**)&wp, g_w);
    cudaGetSymbolAddress((void**)&wf, g_wf);
    cudaGetSymbolAddress((void**)&hf16, g_hf16);
    cudaGetSymbolAddress((void**)&cs, g_colsum);
    cudaGetSymbolAddress((void**)&cq, g_colsumsq);
    __half* aggf16 = (__half*)aggbuf;
    __half* xf16   = (__half*)xfbuf;

    const int SMEM = 3 * 32768;
    cudaFuncSetAttribute(k_mma<256, 1, 0, 0>, cudaFuncAttributeMaxDynamicSharedMemorySize, SMEM);
    cudaFuncSetAttribute(k_mma<256, 1, 0, 1>, cudaFuncAttributeMaxDynamicSharedMemorySize, SMEM);
    cudaFuncSetAttribute(k_mma<128, 0, 1, 0>, cudaFuncAttributeMaxDynamicSharedMemorySize, SMEM);

    // ---- CSR build ----
    k_init<<<(N_NODES + 255) / 256, 256>>>();
    k_hist<<<(N_EDGES + 255) / 256, 256>>>(dstv);
    int nb = (N_NODES + 1023) / 1024;
    k_scan1<<<nb, 1024>>>();
    k_scan2<<<1, 32>>>(nb);
    k_scan3<<<nb, 1024>>>();
    k_fill<<<(N_EDGES + 255) / 256, 256>>>(srcv, dstv);

    // ---- weight + x conversion ----
    {
        ConvJobs j;
        j.W[0] = wl0; j.K[0] = 128; j.N[0] = 256; j.oh[0] = WL0H;  j.ol[0] = WL0L;  j.mode[0] = 0;
        j.W[1] = wr0; j.K[1] = 128; j.N[1] = 256; j.oh[1] = WR0H;  j.ol[1] = WR0L;  j.mode[1] = 0;
        j.W[2] = wl1; j.K[2] = 256; j.N[2] = 256; j.oh[2] = WF1LH; j.ol[2] = WF1LL; j.mode[2] = 1;
        j.W[3] = wr1; j.K[3] = 256; j.N[3] = 256; j.oh[3] = WF1RH; j.ol[3] = WF1RL; j.mode[3] = 1;
        j.W[4] = wl2; j.K[4] = 256; j.N[4] = 256; j.oh[4] = WF2LH; j.ol[4] = WF2LL; j.mode[4] = 1;
        j.W[5] = wr2; j.K[5] = 256; j.N[5] = 256; j.oh[5] = WF2RH; j.ol[5] = WF2RL; j.mode[5] = 1;
        j.W[6] = cw1; j.K[6] = 256; j.N[6] = 128; j.oh[6] = CW1H;  j.ol[6] = CW1L;  j.mode[6] = 0;
        k_convall<<<dim3(256, 7), 256>>>(j, wp, wf);
    }
    k_convx<<<(N_NODES * IN_DIM / 4 + 255) / 256, 256>>>(x, bh2, bl2, xf16);

    int aggGrid = (N_NODES * 32 + 255) / 256;
    int nfGrid  = (N_NODES * HID / 4 + 1023) / 1024;
    int mblocks = (N_NODES + 127) / 128;
    dim3 gMain(2, mblocks);                       // NT=256
    dim3 gCls(1, mblocks);                        // NT=128

    // ---- layer 0 (D=128, bf16 6-seg, exact) ----
    k_agg16_128<<<aggGrid, 256>>>(xf16, bh1, bl1);
    {
        GemmSegs s;
        s.A[0] = bh1; s.W[0] = wp + WL0H;
        s.A[1] = bh1; s.W[1] = wp + WL0L;
        s.A[2] = bl1; s.W[2] = wp + WL0H;
        s.A[3] = bh2; s.W[3] = wp + WR0H;
        s.A[4] = bh2; s.W[4] = wp + WR0L;
        s.A[5] = bl2; s.W[5] = wp + WR0H;
        k_mma<256, 1, 0, 0><<<gMain, 128, SMEM>>>(s, 6, 128, b0, hraw, 0, nullptr, nullptr,
                                                  cs + 0 * HID, cq + 0 * HID);
    }
    k_normfuse<0><<<nfGrid, 256>>>(hraw, g0, be0, cs + 0 * HID, cq + 0 * HID, nullptr, nullptr, hf16);

    // ---- layer 1 (D=256, f16 4-seg) ----
    k_agg16_256<<<aggGrid, 256>>>(hf16, aggf16);
    {
        GemmSegs s;
        s.A[0] = aggf16; s.W[0] = wf + WF1LH;
        s.A[1] = aggf16; s.W[1] = wf + WF1LL;
        s.A[2] = hf16;   s.W[2] = wf + WF1RH;
        s.A[3] = hf16;   s.W[3] = wf + WF1RL;
        s.A[4] = nullptr; s.W[4] = nullptr;
        s.A[5] = nullptr; s.W[5] = nullptr;
        k_mma<256, 1, 0, 1><<<gMain, 128, SMEM>>>(s, 4, 256, b1, hraw, 0, nullptr, nullptr,
                                                  cs + 1 * HID, cq + 1 * HID);
    }
    k_normfuse<0><<<nfGrid, 256>>>(hraw, g1, be1, cs + 1 * HID, cq + 1 * HID, nullptr, nullptr, hf16);

    // ---- layer 2 (D=256, f16 4-seg) ----
    k_agg16_256<<<aggGrid, 256>>>(hf16, aggf16);
    {
        GemmSegs s;
        s.A[0] = aggf16; s.W[0] = wf + WF2LH;
        s.A[1] = aggf16; s.W[1] = wf + WF2LL;
        s.A[2] = hf16;   s.W[2] = wf + WF2RH;
        s.A[3] = hf16;   s.W[3] = wf + WF2RL;
        s.A[4] = nullptr; s.W[4] = nullptr;
        s.A[5] = nullptr; s.W[5] = nullptr;
        k_mma<256, 1, 0, 1><<<gMain, 128, SMEM>>>(s, 4, 256, b2, hraw, 0, nullptr, nullptr,
                                                  cs + 2 * HID, cq + 2 * HID);
    }
    k_normfuse<1><<<nfGrid, 256>>>(hraw, g2, be2, cs + 2 * HID, cq + 2 * HID, bh1, bl1, nullptr);

    // ---- classifier + head fused (bf16 3-seg, exact) ----
    {
        GemmSegs s;
        s.A[0] = bh1; s.W[0] = wp + CW1H;
        s.A[1] = bh1; s.W[1] = wp + CW1L;
        s.A[2] = bl1; s.W[2] = wp + CW1H;
        s.A[3] = nullptr; s.W[3] = nullptr;
        s.A[4] = nullptr; s.W[4] = nullptr;
        s.A[5] = nullptr; s.W[5] = nullptr;
        k_mma<128, 0, 1, 0><<<gCls, 128, SMEM>>>(s, 3, 256, cb1, out, 1, cw2, cb2, nullptr, nullptr);
    }
}

// round 9
// speedup vs baseline: 1.5279x; 1.5279x over previous
#include <cuda_runtime.h>
#include <cuda_bf16.h>
#include <cuda_fp16.h>
#include <cstdint>

#define N_NODES 100000
#define N_EDGES 1600000
#define IN_DIM 128
#define HID 256
#define EPS 1e-5f

// ======================= scratch (static __device__) =======================
__device__ float g_hraw[N_NODES * HID];                 // GEMM output fp32
__device__ __half g_aggf[N_NODES * HID];                // fp16 aggregation buffer
__device__ __half g_xf[N_NODES * IN_DIM];               // fp16 x
__device__ __half g_hf16[N_NODES * HID];                // fp16 h_norm stream
__device__ __half g_wf[720896];                         // fp16 weight pool (hi/lo, W^T [N][K])
__device__ int   g_cnt[N_NODES];
__device__ int   g_cursor[N_NODES];
__device__ int   g_scantmp[N_NODES];
__device__ int   g_rowptr[N_NODES + 1];
__device__ int   g_adj[N_EDGES];
__device__ int   g_bsum[128];
__device__ float g_colsum[3][HID];
__device__ float g_colsumsq[3][HID];

// fp16 pool offsets (elements)
#define WF0LH 0
#define WF0LL 32768
#define WF0RH 65536
#define WF0RL 98304
#define WF1LH 131072
#define WF1LL 196608
#define WF1RH 262144
#define WF1RL 327680
#define WF2LH 393216
#define WF2LL 458752
#define WF2RH 524288
#define WF2RL 589824
#define CW1H  655360
#define CW1L  688128

__device__ __forceinline__ uint32_t smem_u32(const void* p) {
    uint32_t a;
    asm("{ .reg .u64 t; cvta.to.shared.u64 t, %1; cvt.u32.u64 %0, t; }" : "=r"(a) : "l"(p));
    return a;
}

// ======================= CSR build =======================
__global__ void k_init() {
    int i = blockIdx.x * blockDim.x + threadIdx.x;
    if (i < N_NODES) { g_cnt[i] = 0; g_cursor[i] = 0; }
    if (i < HID) {
        #pragma unroll
        for (int l = 0; l < 3; l++) { g_colsum[l][i] = 0.f; g_colsumsq[l][i] = 0.f; }
    }
}
__global__ void k_hist(const int* __restrict__ dst) {
    int e = blockIdx.x * blockDim.x + threadIdx.x;
    if (e < N_EDGES) atomicAdd(&g_cnt[dst[e]], 1);
}
__global__ void k_scan1() {
    __shared__ int s[1024];
    int i = blockIdx.x * 1024 + threadIdx.x;
    int v = (i < N_NODES) ? g_cnt[i] : 0;
    s[threadIdx.x] = v;
    __syncthreads();
    #pragma unroll
    for (int off = 1; off < 1024; off <<= 1) {
        int t = (threadIdx.x >= off) ? s[threadIdx.x - off] : 0;
        __syncthreads();
        s[threadIdx.x] += t;
        __syncthreads();
    }
    if (i < N_NODES) g_scantmp[i] = s[threadIdx.x];
    if (threadIdx.x == 1023) g_bsum[blockIdx.x] = s[1023];
}
__global__ void k_scan2(int nb) {
    if (threadIdx.x == 0 && blockIdx.x == 0) {
        int acc = 0;
        for (int i = 0; i < nb; i++) { int v = g_bsum[i]; g_bsum[i] = acc; acc += v; }
    }
}
__global__ void k_scan3() {
    int i = blockIdx.x * 1024 + threadIdx.x;
    if (i < N_NODES) {
        g_rowptr[i + 1] = g_scantmp[i] + g_bsum[blockIdx.x];
        if (i == 0) g_rowptr[0] = 0;
    }
}
__global__ void k_fill(const int* __restrict__ src, const int* __restrict__ dst) {
    int e = blockIdx.x * blockDim.x + threadIdx.x;
    if (e < N_EDGES) {
        int d = dst[e];
        int pos = g_rowptr[d] + atomicAdd(&g_cursor[d], 1);
        g_adj[pos] = src[e];
    }
}

// ======================= aggregation =======================
// L0: fp16 x [N,128] gather -> fp16 [N,128]. warp/node, lane = 4 cols.
__global__ void k_agg16_128(const __half* __restrict__ xf, __half* __restrict__ o16) {
    int w = (blockIdx.x * blockDim.x + threadIdx.x) >> 5;
    int lane = threadIdx.x & 31;
    if (w >= N_NODES) return;
    int s0 = g_rowptr[w], s1 = g_rowptr[w + 1];
    float a0 = 0.f, a1 = 0.f, a2 = 0.f, a3 = 0.f;
    for (int e = s0; e < s1; e++) {
        uint2 v = *(const uint2*)(xf + (size_t)g_adj[e] * IN_DIM + lane * 4);
        float2 f0 = __half22float2(*(const __half2*)&v.x);
        float2 f1 = __half22float2(*(const __half2*)&v.y);
        a0 += f0.x; a1 += f0.y; a2 += f1.x; a3 += f1.y;
    }
    int deg = s1 - s0;
    float inv = 1.f / (float)(deg > 0 ? deg : 1);
    __half2 h0 = __floats2half2_rn(a0 * inv, a1 * inv);
    __half2 h1 = __floats2half2_rn(a2 * inv, a3 * inv);
    uint2 u;
    u.x = *(uint32_t*)&h0; u.y = *(uint32_t*)&h1;
    *(uint2*)(o16 + (size_t)w * IN_DIM + lane * 4) = u;
}

// L1/L2: fp16 [N,256] gather -> fp16 [N,256]. warp/node, lane = 8 cols.
__global__ void k_agg16_256(const __half* __restrict__ xf, __half* __restrict__ o16) {
    int w = (blockIdx.x * blockDim.x + threadIdx.x) >> 5;
    int lane = threadIdx.x & 31;
    if (w >= N_NODES) return;
    int s0 = g_rowptr[w], s1 = g_rowptr[w + 1];
    float acc[8];
    #pragma unroll
    for (int i = 0; i < 8; i++) acc[i] = 0.f;
    for (int e = s0; e < s1; e++) {
        size_t base = (size_t)g_adj[e] * HID + lane * 8;
        uint4 v = *(const uint4*)(xf + base);
        const uint32_t* p = &v.x;
        #pragma unroll
        for (int i = 0; i < 4; i++) {
            float2 f = __half22float2(*(const __half2*)&p[i]);
            acc[i * 2 + 0] += f.x;
            acc[i * 2 + 1] += f.y;
        }
    }
    int deg = s1 - s0;
    float inv = 1.f / (float)(deg > 0 ? deg : 1);
    uint4 u;
    uint32_t* p = &u.x;
    #pragma unroll
    for (int i = 0; i < 4; i++) {
        __half2 h = __floats2half2_rn(acc[i * 2] * inv, acc[i * 2 + 1] * inv);
        p[i] = *(uint32_t*)&h;
    }
    *(uint4*)(o16 + (size_t)w * HID + lane * 8) = u;
}

// ======================= conversions =======================
// x fp32 [N,128] -> fp16
__global__ void k_convx(const float* __restrict__ x, __half* __restrict__ o16) {
    int i = blockIdx.x * blockDim.x + threadIdx.x;   // float4 index
    if (i >= N_NODES * IN_DIM / 4) return;
    float4 v = ((const float4*)x)[i];
    __half2 f0 = __floats2half2_rn(v.x, v.y);
    __half2 f1 = __floats2half2_rn(v.z, v.w);
    uint2 uf;
    uf.x = *(uint32_t*)&f0; uf.y = *(uint32_t*)&f1;
    ((uint2*)o16)[i] = uf;
}

// weights: fp32 [K,N] -> W^T fp16 hi/lo [N][K]
struct ConvJobs { const float* W[7]; int K[7]; int N[7]; int oh[7]; int ol[7]; };
__global__ void k_convall(ConvJobs j, __half* __restrict__ wf) {
    int s = blockIdx.y;
    int K = j.K[s], N = j.N[s];
    int id = blockIdx.x * blockDim.x + threadIdx.x;
    if (id >= K * N) return;
    int k = id / N, n = id % N;
    float v = __ldg(&j.W[s][id]);
    size_t pos = (size_t)n * K + k;
    __half h = __float2half_rn(v);
    wf[j.oh[s] + pos] = h;
    wf[j.ol[s] + pos] = __float2half_rn(v - __half2float(h));
}

// ======================= f16 mma.sync GEMM (R7-proven config) =======================
// 256 threads, 8 warps 4x2, warp tile 32x64, BM=128, BN=128, BK=64, 3-stage.
struct GemmSegs { const void* A[4]; const void* W[4]; };

#define MMA_F16(c, a, b0v, b1v) \
    asm volatile("mma.sync.aligned.m16n8k16.row.col.f32.f16.f16.f32 " \
        "{%0,%1,%2,%3}, {%4,%5,%6,%7}, {%8,%9}, {%0,%1,%2,%3};" \
        : "+f"((c)[0]), "+f"((c)[1]), "+f"((c)[2]), "+f"((c)[3]) \
        : "r"((a)[0]), "r"((a)[1]), "r"((a)[2]), "r"((a)[3]), "r"(b0v), "r"(b1v))

template <int NT, int STATS, int FINAL>
__global__ __launch_bounds__(256, 2)
void k_mma(GemmSegs segs, int nseg, int D, const float* __restrict__ bias,
           float* __restrict__ C, int relu,
           const float* __restrict__ w2, const float* __restrict__ b2,
           float* __restrict__ csum, float* __restrict__ cqsum) {
    extern __shared__ char dsm[];                 // 3 stages x [A 16KB | B 16KB]
    __shared__ float scol[128], scolq[128];
    __shared__ float srow[256];
    __shared__ float s_w2[256];
    const uint32_t sb = smem_u32(dsm);
    const int tid = threadIdx.x;
    const int lane = tid & 31, wid = tid >> 5;
    const int wm = wid & 3, wn = wid >> 2;        // 4 m-warps x 2 n-warps
    const int bm0 = blockIdx.y * 128, bn0 = blockIdx.x * 128;
    const int grp = lane >> 3, tg = lane & 7;

    if (STATS && tid < 128) { scol[tid] = 0.f; scolq[tid] = 0.f; }
    if (FINAL && tid < 256) { srow[tid] = 0.f; s_w2[tid] = __ldg(&w2[tid]); }

    const int cpsLog = (D == 256) ? 2 : 1;
    const int nkb = nseg << cpsLog;

    const uint32_t xr = (uint32_t)tg << 4;
    const int rowA0 = wm * 32 + tg + (grp & 1) * 8;
    const int rowB0 = wn * 64 + tg + (grp >> 1) * 8;
    const uint32_t kA = (uint32_t)(grp >> 1) * 16;
    const uint32_t kB = (uint32_t)(grp & 1) * 16;

    float acc[2][8][4];
    #pragma unroll
    for (int mt = 0; mt < 2; mt++)
        #pragma unroll
        for (int nt = 0; nt < 8; nt++)
            #pragma unroll
            for (int j = 0; j < 4; j++) acc[mt][nt][j] = 0.f;

    auto load_stage = [&](int kb, int st) {
        int seg = kb >> cpsLog;
        int koff = (kb & ((1 << cpsLog) - 1)) << 6;
        const uint16_t* Aseg = (const uint16_t*)segs.A[seg];
        const uint16_t* Wseg = (const uint16_t*)segs.W[seg];
        uint32_t sA = sb + (uint32_t)st * 32768u;
        uint32_t sB = sA + 16384u;
        #pragma unroll
        for (int t = 0; t < 4; t++) {
            int idx = tid + t * 256;
            int row = idx >> 3, ch = idx & 7;
            uint32_t swz = (uint32_t)row * 128u + (((uint32_t)ch * 16u) ^ (((uint32_t)row & 7u) << 4));
            int grow = bm0 + row;
            int ok = grow < N_NODES;
            const void* gA = Aseg + (size_t)(ok ? grow : 0) * D + koff + ch * 8;
            int sz = ok ? 16 : 0;
            asm volatile("cp.async.cg.shared.global [%0], [%1], 16, %2;"
                         :: "r"(sA + swz), "l"(gA), "r"(sz));
            const void* gB = Wseg + (size_t)(bn0 + row) * D + koff + ch * 8;
            asm volatile("cp.async.cg.shared.global [%0], [%1], 16;"
                         :: "r"(sB + swz), "l"(gB));
        }
        asm volatile("cp.async.commit_group;");
    };

    auto compute_stage = [&](int st) {
        uint32_t aBase = sb + (uint32_t)st * 32768u + (uint32_t)rowA0 * 128u;
        uint32_t bBase = sb + (uint32_t)st * 32768u + 16384u + (uint32_t)rowB0 * 128u;
        #pragma unroll
        for (int kt = 0; kt < 4; kt++) {
            uint32_t a[2][4];
            #pragma unroll
            for (int mt = 0; mt < 2; mt++) {
                uint32_t ad = aBase + (uint32_t)mt * 2048u + (((uint32_t)kt * 32u + kA) ^ xr);
                asm volatile("ldmatrix.sync.aligned.m8n8.x4.shared.b16 {%0,%1,%2,%3}, [%4];"
                    : "=r"(a[mt][0]), "=r"(a[mt][1]), "=r"(a[mt][2]), "=r"(a[mt][3]) : "r"(ad));
            }
            #pragma unroll
            for (int np = 0; np < 4; np++) {
                uint32_t b0, b1, b2r, b3;
                uint32_t bd = bBase + (uint32_t)np * 2048u + (((uint32_t)kt * 32u + kB) ^ xr);
                asm volatile("ldmatrix.sync.aligned.m8n8.x4.shared.b16 {%0,%1,%2,%3}, [%4];"
                    : "=r"(b0), "=r"(b1), "=r"(b2r), "=r"(b3) : "r"(bd));
                #pragma unroll
                for (int mt = 0; mt < 2; mt++) {
                    MMA_F16(acc[mt][np * 2 + 0], a[mt], b0, b1);
                    MMA_F16(acc[mt][np * 2 + 1], a[mt], b2r, b3);
                }
            }
        }
    };

    load_stage(0, 0);
    load_stage(1, 1);
    int st = 0;
    for (int kb = 0; kb < nkb; kb++) {
        if (kb < nkb - 1) asm volatile("cp.async.wait_group 1;");
        else              asm volatile("cp.async.wait_group 0;");
        __syncthreads();
        compute_stage(st);
        if (kb + 2 < nkb) {
            int st2 = st + 2; if (st2 >= 3) st2 -= 3;
            load_stage(kb + 2, st2);
        }
        if (++st == 3) st = 0;
    }

    // ---- epilogue ----
    const int rbase = wm * 32 + (lane >> 2);
    const int cbL = wn * 64 + (lane & 3) * 2;
    float po[8];
    #pragma unroll
    for (int i = 0; i < 8; i++) po[i] = 0.f;

    #pragma unroll
    for (int nt = 0; nt < 8; nt++) {
        int colL = cbL + nt * 8;
        int col = bn0 + colL;
        float bv0 = __ldg(&bias[col]), bv1 = __ldg(&bias[col + 1]);
        float s0 = 0.f, s1 = 0.f, q0 = 0.f, q1 = 0.f;
        #pragma unroll
        for (int mt = 0; mt < 2; mt++) {
            int row = bm0 + rbase + mt * 16;
            float h0 = acc[mt][nt][0] + bv0, h1 = acc[mt][nt][1] + bv1;
            float h2 = acc[mt][nt][2] + bv0, h3 = acc[mt][nt][3] + bv1;
            if (relu) {
                h0 = fmaxf(h0, 0.f); h1 = fmaxf(h1, 0.f);
                h2 = fmaxf(h2, 0.f); h3 = fmaxf(h3, 0.f);
            }
            bool v0 = row < N_NODES, v1 = (row + 8) < N_NODES;
            if (STATS) {
                float a0 = v0 ? h0 : 0.f, a1 = v0 ? h1 : 0.f;
                float a2 = v1 ? h2 : 0.f, a3 = v1 ? h3 : 0.f;
                s0 += a0 + a2; s1 += a1 + a3;
                q0 += a0 * a0 + a2 * a2; q1 += a1 * a1 + a3 * a3;
            }
            if (!FINAL) {
                if (v0) *(float2*)(C + (size_t)row * NT + col) = make_float2(h0, h1);
                if (v1) *(float2*)(C + (size_t)(row + 8) * NT + col) = make_float2(h2, h3);
            } else {
                float w20 = s_w2[colL * 2], w21 = s_w2[colL * 2 + 1];
                float w30 = s_w2[(colL + 1) * 2], w31 = s_w2[(colL + 1) * 2 + 1];
                po[mt * 4 + 0] += h0 * w20 + h1 * w30;
                po[mt * 4 + 1] += h0 * w21 + h1 * w31;
                po[mt * 4 + 2] += h2 * w20 + h3 * w30;
                po[mt * 4 + 3] += h2 * w21 + h3 * w31;
            }
        }
        if (STATS) {
            #pragma unroll
            for (int off = 4; off <= 16; off <<= 1) {
                s0 += __shfl_xor_sync(0xffffffffu, s0, off);
                s1 += __shfl_xor_sync(0xffffffffu, s1, off);
                q0 += __shfl_xor_sync(0xffffffffu, q0, off);
                q1 += __shfl_xor_sync(0xffffffffu, q1, off);
            }
            if ((lane >> 2) == 0) {
                atomicAdd(&scol[colL], s0);  atomicAdd(&scol[colL + 1], s1);
                atomicAdd(&scolq[colL], q0); atomicAdd(&scolq[colL + 1], q1);
            }
        }
    }
    if (STATS) {
        __syncthreads();
        if (tid < 128) {
            atomicAdd(&csum[bn0 + tid], scol[tid]);
            atomicAdd(&cqsum[bn0 + tid], scolq[tid]);
        }
    }
    if (FINAL) {
        #pragma unroll
        for (int mt = 0; mt < 2; mt++) {
            int rl = rbase + mt * 16;
            atomicAdd(&srow[rl * 2 + 0], po[mt * 4 + 0]);
            atomicAdd(&srow[rl * 2 + 1], po[mt * 4 + 1]);
            atomicAdd(&srow[(rl + 8) * 2 + 0], po[mt * 4 + 2]);
            atomicAdd(&srow[(rl + 8) * 2 + 1], po[mt * 4 + 3]);
        }
        __syncthreads();
        if (tid < 128) {
            int grow = bm0 + tid;
            if (grow < N_NODES) {
                C[(size_t)grow * 2 + 0] = srow[tid * 2 + 0] + __ldg(&b2[0]);
                C[(size_t)grow * 2 + 1] = srow[tid * 2 + 1] + __ldg(&b2[1]);
            }
        }
    }
}

// ======== normalize + relu -> fp16 stream (BN affine inline) ========
__global__ void k_normfuse(const float* __restrict__ h,
                           const float* __restrict__ g, const float* __restrict__ be,
                           const float* __restrict__ csum, const float* __restrict__ cqsum,
                           __half* __restrict__ of) {
    __shared__ float sna[HID], snc[HID];
    int tid = threadIdx.x;
    {
        float cs = csum[tid], cq = cqsum[tid];
        float mu  = cs / (float)N_NODES;
        float var = cq / (float)N_NODES - mu * mu;
        var = fmaxf(var, 0.f);
        float a = __ldg(&g[tid]) * rsqrtf(var + EPS);
        sna[tid] = a;
        snc[tid] = __ldg(&be[tid]) - mu * a;
    }
    __syncthreads();
    #pragma unroll
    for (int pass = 0; pass < 4; pass++) {
        int i = blockIdx.x * 1024 + pass * 256 + tid;    // float4 index
        if (i >= N_NODES * HID / 4) return;
        float4 v = ((const float4*)h)[i];
        int cidx = (i * 4) & (HID - 1);
        v.x = fmaxf(v.x * sna[cidx + 0] + snc[cidx + 0], 0.f);
        v.y = fmaxf(v.y * sna[cidx + 1] + snc[cidx + 1], 0.f);
        v.z = fmaxf(v.z * sna[cidx + 2] + snc[cidx + 2], 0.f);
        v.w = fmaxf(v.w * sna[cidx + 3] + snc[cidx + 3], 0.f);
        __half2 f0 = __floats2half2_rn(v.x, v.y);
        __half2 f1 = __floats2half2_rn(v.z, v.w);
        uint2 uf;
        uf.x = *(uint32_t*)&f0; uf.y = *(uint32_t*)&f1;
        ((uint2*)of)[i] = uf;
    }
}

// ======================= launch =======================
extern "C" void kernel_launch(void* const* d_in, const int* in_sizes, int n_in,
                              void* d_out, int out_size) {
    const float* x    = (const float*)d_in[0];
    const int*   ei   = (const int*)d_in[1];   // int32 (JAX x64 disabled)
    const int*   srcv = ei;
    const int*   dstv = ei + N_EDGES;
    const float* wl0 = (const float*)d_in[2];
    const float* wr0 = (const float*)d_in[3];
    const float* b0  = (const float*)d_in[4];
    const float* g0  = (const float*)d_in[5];
    const float* be0 = (const float*)d_in[6];
    const float* wl1 = (const float*)d_in[7];
    const float* wr1 = (const float*)d_in[8];
    const float* b1  = (const float*)d_in[9];
    const float* g1  = (const float*)d_in[10];
    const float* be1 = (const float*)d_in[11];
    const float* wl2 = (const float*)d_in[12];
    const float* wr2 = (const float*)d_in[13];
    const float* b2  = (const float*)d_in[14];
    const float* g2  = (const float*)d_in[15];
    const float* be2 = (const float*)d_in[16];
    const float* cw1 = (const float*)d_in[17];
    const float* cb1 = (const float*)d_in[18];
    const float* cw2 = (const float*)d_in[19];
    const float* cb2 = (const float*)d_in[20];
    float* out = (float*)d_out;

    float* hraw;
    __half *aggf, *xf16, *hf16, *wf;
    float *cs, *cq;
    cudaGetSymbolAddress((void**)&hraw, g_hraw);
    cudaGetSymbolAddress((void**)&aggf, g_aggf);
    cudaGetSymbolAddress((void**)&xf16, g_xf);
    cudaGetSymbolAddress((void**)&hf16, g_hf16);
    cudaGetSymbolAddress((void**)&wf, g_wf);
    cudaGetSymbolAddress((void**)&cs, g_colsum);
    cudaGetSymbolAddress((void**)&cq, g_colsumsq);

    const int SMEM = 3 * 32768;
    cudaFuncSetAttribute(k_mma<256, 1, 0>, cudaFuncAttributeMaxDynamicSharedMemorySize, SMEM);
    cudaFuncSetAttribute(k_mma<128, 0, 1>, cudaFuncAttributeMaxDynamicSharedMemorySize, SMEM);

    // ---- CSR build ----
    k_init<<<(N_NODES + 255) / 256, 256>>>();
    k_hist<<<(N_EDGES + 255) / 256, 256>>>(dstv);
    int nb = (N_NODES + 1023) / 1024;
    k_scan1<<<nb, 1024>>>();
    k_scan2<<<1, 32>>>(nb);
    k_scan3<<<nb, 1024>>>();
    k_fill<<<(N_EDGES + 255) / 256, 256>>>(srcv, dstv);

    // ---- weight + x conversion (all fp16 hi/lo) ----
    {
        ConvJobs j;
        j.W[0] = wl0; j.K[0] = 128; j.N[0] = 256; j.oh[0] = WF0LH; j.ol[0] = WF0LL;
        j.W[1] = wr0; j.K[1] = 128; j.N[1] = 256; j.oh[1] = WF0RH; j.ol[1] = WF0RL;
        j.W[2] = wl1; j.K[2] = 256; j.N[2] = 256; j.oh[2] = WF1LH; j.ol[2] = WF1LL;
        j.W[3] = wr1; j.K[3] = 256; j.N[3] = 256; j.oh[3] = WF1RH; j.ol[3] = WF1RL;
        j.W[4] = wl2; j.K[4] = 256; j.N[4] = 256; j.oh[4] = WF2LH; j.ol[4] = WF2LL;
        j.W[5] = wr2; j.K[5] = 256; j.N[5] = 256; j.oh[5] = WF2RH; j.ol[5] = WF2RL;
        j.W[6] = cw1; j.K[6] = 256; j.N[6] = 128; j.oh[6] = CW1H;  j.ol[6] = CW1L;
        k_convall<<<dim3(256, 7), 256>>>(j, wf);
    }
    k_convx<<<(N_NODES * IN_DIM / 4 + 255) / 256, 256>>>(x, xf16);

    int aggGrid = (N_NODES * 32 + 255) / 256;
    int nfGrid  = (N_NODES * HID / 4 + 1023) / 1024;
    int mblocks = (N_NODES + 127) / 128;
    dim3 gMain(2, mblocks);                       // NT=256
    dim3 gCls(1, mblocks);                        // NT=128

    // ---- layer 0 (D=128, f16 4-seg: agg@wl0(hi,lo) + x@wr0(hi,lo)) ----
    k_agg16_128<<<aggGrid, 256>>>(xf16, aggf);
    {
        GemmSegs s;
        s.A[0] = aggf; s.W[0] = wf + WF0LH;
        s.A[1] = aggf; s.W[1] = wf + WF0LL;
        s.A[2] = xf16; s.W[2] = wf + WF0RH;
        s.A[3] = xf16; s.W[3] = wf + WF0RL;
        k_mma<256, 1, 0><<<gMain, 256, SMEM>>>(s, 4, 128, b0, hraw, 0, nullptr, nullptr,
                                               cs + 0 * HID, cq + 0 * HID);
    }
    k_normfuse<<<nfGrid, 256>>>(hraw, g0, be0, cs + 0 * HID, cq + 0 * HID, hf16);

    // ---- layer 1 (D=256, f16 4-seg) ----
    k_agg16_256<<<aggGrid, 256>>>(hf16, aggf);
    {
        GemmSegs s;
        s.A[0] = aggf; s.W[0] = wf + WF1LH;
        s.A[1] = aggf; s.W[1] = wf + WF1LL;
        s.A[2] = hf16; s.W[2] = wf + WF1RH;
        s.A[3] = hf16; s.W[3] = wf + WF1RL;
        k_mma<256, 1, 0><<<gMain, 256, SMEM>>>(s, 4, 256, b1, hraw, 0, nullptr, nullptr,
                                               cs + 1 * HID, cq + 1 * HID);
    }
    k_normfuse<<<nfGrid, 256>>>(hraw, g1, be1, cs + 1 * HID, cq + 1 * HID, hf16);

    // ---- layer 2 (D=256, f16 4-seg) ----
    k_agg16_256<<<aggGrid, 256>>>(hf16, aggf);
    {
        GemmSegs s;
        s.A[0] = aggf; s.W[0] = wf + WF2LH;
        s.A[1] = aggf; s.W[1] = wf + WF2LL;
        s.A[2] = hf16; s.W[2] = wf + WF2RH;
        s.A[3] = hf16; s.W[3] = wf + WF2RL;
        k_mma<256, 1, 0><<<gMain, 256, SMEM>>>(s, 4, 256, b2, hraw, 0, nullptr, nullptr,
                                               cs + 2 * HID, cq + 2 * HID);
    }
    k_normfuse<<<nfGrid, 256>>>(hraw, g2, be2, cs + 2 * HID, cq + 2 * HID, hf16);

    // ---- classifier + head fused (f16 2-seg): out = relu(h2@cw1+cb1) @ cw2 + cb2 ----
    {
        GemmSegs s;
        s.A[0] = hf16; s.W[0] = wf + CW1H;
        s.A[1] = hf16; s.W[1] = wf + CW1L;
        s.A[2] = nullptr; s.W[2] = nullptr;
        s.A[3] = nullptr; s.W[3] = nullptr;
        k_mma<128, 0, 1><<<gCls, 256, SMEM>>>(s, 2, 256, cb1, out, 1, cw2, cb2, nullptr, nullptr);
    }
}

// round 10
// speedup vs baseline: 1.6574x; 1.0847x over previous
#include <cuda_runtime.h>
#include <cuda_bf16.h>
#include <cuda_fp16.h>
#include <cstdint>

#define N_NODES 100000
#define N_EDGES 1600000
#define IN_DIM 128
#define HID 256
#define EPS 1e-5f

// ======================= scratch (static __device__) =======================
__device__ float g_hraw[N_NODES * HID];                 // GEMM output fp32
__device__ __half g_aggf[N_NODES * HID];                // fp16 aggregation buffer
__device__ __half g_xf[N_NODES * IN_DIM];               // fp16 x
__device__ __half g_hf16[N_NODES * HID];                // fp16 h_norm stream
__device__ __half g_wf[720896];                         // fp16 weight pool (hi/lo, W^T [N][K])
__device__ int   g_cnt[N_NODES];
__device__ int   g_cursor[N_NODES];
__device__ int   g_scantmp[N_NODES];
__device__ int   g_rowptr[N_NODES + 1];
__device__ int   g_adj[N_EDGES];
__device__ int   g_bsum[128];
__device__ float g_colsum[3][HID];
__device__ float g_colsumsq[3][HID];

// fp16 pool offsets (elements)
#define WF0LH 0
#define WF0LL 32768
#define WF0RH 65536
#define WF0RL 98304
#define WF1LH 131072
#define WF1LL 196608
#define WF1RH 262144
#define WF1RL 327680
#define WF2LH 393216
#define WF2LL 458752
#define WF2RH 524288
#define WF2RL 589824
#define CW1H  655360
#define CW1L  688128

__device__ __forceinline__ uint32_t smem_u32(const void* p) {
    uint32_t a;
    asm("{ .reg .u64 t; cvta.to.shared.u64 t, %1; cvt.u32.u64 %0, t; }" : "=r"(a) : "l"(p));
    return a;
}

// ======================= CSR build =======================
__global__ void k_init() {
    int i = blockIdx.x * blockDim.x + threadIdx.x;
    if (i < N_NODES) { g_cnt[i] = 0; g_cursor[i] = 0; }
    if (i < HID) {
        #pragma unroll
        for (int l = 0; l < 3; l++) { g_colsum[l][i] = 0.f; g_colsumsq[l][i] = 0.f; }
    }
}
__global__ void k_hist(const int* __restrict__ dst) {
    int e = blockIdx.x * blockDim.x + threadIdx.x;
    if (e < N_EDGES) atomicAdd(&g_cnt[dst[e]], 1);
}
__global__ void k_scan1() {
    __shared__ int s[1024];
    int i = blockIdx.x * 1024 + threadIdx.x;
    int v = (i < N_NODES) ? g_cnt[i] : 0;
    s[threadIdx.x] = v;
    __syncthreads();
    #pragma unroll
    for (int off = 1; off < 1024; off <<= 1) {
        int t = (threadIdx.x >= off) ? s[threadIdx.x - off] : 0;
        __syncthreads();
        s[threadIdx.x] += t;
        __syncthreads();
    }
    if (i < N_NODES) g_scantmp[i] = s[threadIdx.x];
    if (threadIdx.x == 1023) g_bsum[blockIdx.x] = s[1023];
}
// parallel exclusive scan over nb (<=128) block sums, one 128-thread block
__global__ void k_scan2(int nb) {
    __shared__ int s[128];
    int t = threadIdx.x;
    int v = (t < nb) ? g_bsum[t] : 0;
    s[t] = v;
    __syncthreads();
    #pragma unroll
    for (int off = 1; off < 128; off <<= 1) {
        int u = (t >= off) ? s[t - off] : 0;
        __syncthreads();
        s[t] += u;
        __syncthreads();
    }
    if (t < nb) g_bsum[t] = s[t] - v;   // exclusive
}
__global__ void k_scan3() {
    int i = blockIdx.x * 1024 + threadIdx.x;
    if (i < N_NODES) {
        g_rowptr[i + 1] = g_scantmp[i] + g_bsum[blockIdx.x];
        if (i == 0) g_rowptr[0] = 0;
    }
}
__global__ void k_fill(const int* __restrict__ src, const int* __restrict__ dst) {
    int e = blockIdx.x * blockDim.x + threadIdx.x;
    if (e < N_EDGES) {
        int d = dst[e];
        int pos = g_rowptr[d] + atomicAdd(&g_cursor[d], 1);
        g_adj[pos] = src[e];
    }
}

// ======================= aggregation =======================
// L0: fp16 x [N,128] gather -> fp16 [N,128]. warp/node, lane = 4 cols, 2-edge unroll.
__global__ void k_agg16_128(const __half* __restrict__ xf, __half* __restrict__ o16) {
    int w = (blockIdx.x * blockDim.x + threadIdx.x) >> 5;
    int lane = threadIdx.x & 31;
    if (w >= N_NODES) return;
    int s0 = g_rowptr[w], s1 = g_rowptr[w + 1];
    float a0 = 0.f, a1 = 0.f, a2 = 0.f, a3 = 0.f;
    int e = s0;
    for (; e + 2 <= s1; e += 2) {
        int na = g_adj[e], nb2 = g_adj[e + 1];
        uint2 va = *(const uint2*)(xf + (size_t)na * IN_DIM + lane * 4);
        uint2 vb = *(const uint2*)(xf + (size_t)nb2 * IN_DIM + lane * 4);
        float2 fa0 = __half22float2(*(const __half2*)&va.x);
        float2 fa1 = __half22float2(*(const __half2*)&va.y);
        float2 fb0 = __half22float2(*(const __half2*)&vb.x);
        float2 fb1 = __half22float2(*(const __half2*)&vb.y);
        a0 += fa0.x + fb0.x; a1 += fa0.y + fb0.y;
        a2 += fa1.x + fb1.x; a3 += fa1.y + fb1.y;
    }
    if (e < s1) {
        uint2 v = *(const uint2*)(xf + (size_t)g_adj[e] * IN_DIM + lane * 4);
        float2 f0 = __half22float2(*(const __half2*)&v.x);
        float2 f1 = __half22float2(*(const __half2*)&v.y);
        a0 += f0.x; a1 += f0.y; a2 += f1.x; a3 += f1.y;
    }
    int deg = s1 - s0;
    float inv = 1.f / (float)(deg > 0 ? deg : 1);
    __half2 h0 = __floats2half2_rn(a0 * inv, a1 * inv);
    __half2 h1 = __floats2half2_rn(a2 * inv, a3 * inv);
    uint2 u;
    u.x = *(uint32_t*)&h0; u.y = *(uint32_t*)&h1;
    *(uint2*)(o16 + (size_t)w * IN_DIM + lane * 4) = u;
}

// L1/L2: fp16 [N,256] gather -> fp16 [N,256]. warp/node, lane = 8 cols, 2-edge unroll.
__global__ void k_agg16_256(const __half* __restrict__ xf, __half* __restrict__ o16) {
    int w = (blockIdx.x * blockDim.x + threadIdx.x) >> 5;
    int lane = threadIdx.x & 31;
    if (w >= N_NODES) return;
    int s0 = g_rowptr[w], s1 = g_rowptr[w + 1];
    float acc[8];
    #pragma unroll
    for (int i = 0; i < 8; i++) acc[i] = 0.f;
    int e = s0;
    for (; e + 2 <= s1; e += 2) {
        size_t ba = (size_t)g_adj[e] * HID + lane * 8;
        size_t bb = (size_t)g_adj[e + 1] * HID + lane * 8;
        uint4 va = *(const uint4*)(xf + ba);
        uint4 vb = *(const uint4*)(xf + bb);
        const uint32_t* pa = &va.x;
        const uint32_t* pb = &vb.x;
        #pragma unroll
        for (int i = 0; i < 4; i++) {
            float2 fa = __half22float2(*(const __half2*)&pa[i]);
            float2 fb = __half22float2(*(const __half2*)&pb[i]);
            acc[i * 2 + 0] += fa.x + fb.x;
            acc[i * 2 + 1] += fa.y + fb.y;
        }
    }
    if (e < s1) {
        size_t base = (size_t)g_adj[e] * HID + lane * 8;
        uint4 v = *(const uint4*)(xf + base);
        const uint32_t* p = &v.x;
        #pragma unroll
        for (int i = 0; i < 4; i++) {
            float2 f = __half22float2(*(const __half2*)&p[i]);
            acc[i * 2 + 0] += f.x;
            acc[i * 2 + 1] += f.y;
        }
    }
    int deg = s1 - s0;
    float inv = 1.f / (float)(deg > 0 ? deg : 1);
    uint4 u;
    uint32_t* p = &u.x;
    #pragma unroll
    for (int i = 0; i < 4; i++) {
        __half2 h = __floats2half2_rn(acc[i * 2] * inv, acc[i * 2 + 1] * inv);
        p[i] = *(uint32_t*)&h;
    }
    *(uint4*)(o16 + (size_t)w * HID + lane * 8) = u;
}

// ======================= conversions =======================
__global__ void k_convx(const float* __restrict__ x, __half* __restrict__ o16) {
    int i = blockIdx.x * blockDim.x + threadIdx.x;   // float4 index
    if (i >= N_NODES * IN_DIM / 4) return;
    float4 v = ((const float4*)x)[i];
    __half2 f0 = __floats2half2_rn(v.x, v.y);
    __half2 f1 = __floats2half2_rn(v.z, v.w);
    uint2 uf;
    uf.x = *(uint32_t*)&f0; uf.y = *(uint32_t*)&f1;
    ((uint2*)o16)[i] = uf;
}

// weights: fp32 [K,N] -> W^T fp16 hi/lo [N][K]
struct ConvJobs { const float* W[7]; int K[7]; int N[7]; int oh[7]; int ol[7]; };
__global__ void k_convall(ConvJobs j, __half* __restrict__ wf) {
    int s = blockIdx.y;
    int K = j.K[s], N = j.N[s];
    int id = blockIdx.x * blockDim.x + threadIdx.x;
    if (id >= K * N) return;
    int k = id / N, n = id % N;
    float v = __ldg(&j.W[s][id]);
    size_t pos = (size_t)n * K + k;
    __half h = __float2half_rn(v);
    wf[j.oh[s] + pos] = h;
    wf[j.ol[s] + pos] = __float2half_rn(v - __half2float(h));
}

// ======================= f16 mma.sync GEMM =======================
// 256 threads, 8 warps 4x2, warp tile 32x64, BM=128, BN=128, BK=64, 3-stage.
struct GemmSegs { const void* A[4]; const void* W[4]; };

#define MMA_F16(c, a, b0v, b1v) \
    asm volatile("mma.sync.aligned.m16n8k16.row.col.f32.f16.f16.f32 " \
        "{%0,%1,%2,%3}, {%4,%5,%6,%7}, {%8,%9}, {%0,%1,%2,%3};" \
        : "+f"((c)[0]), "+f"((c)[1]), "+f"((c)[2]), "+f"((c)[3]) \
        : "r"((a)[0]), "r"((a)[1]), "r"((a)[2]), "r"((a)[3]), "r"(b0v), "r"(b1v))

template <int NT, int STATS, int FINAL>
__global__ __launch_bounds__(256, 2)
void k_mma(GemmSegs segs, int nseg, int D, const float* __restrict__ bias,
           float* __restrict__ C, int relu,
           const float* __restrict__ w2, const float* __restrict__ b2,
           float* __restrict__ csum, float* __restrict__ cqsum) {
    extern __shared__ char dsm[];                 // 3 stages x [A 16KB | B 16KB]
    __shared__ float scol[128], scolq[128];
    __shared__ float srow[256];
    __shared__ float s_w2[256];
    const uint32_t sb = smem_u32(dsm);
    const int tid = threadIdx.x;
    const int lane = tid & 31, wid = tid >> 5;
    const int wm = wid & 3, wn = wid >> 2;        // 4 m-warps x 2 n-warps
    const int bm0 = blockIdx.y * 128, bn0 = blockIdx.x * 128;
    const int grp = lane >> 3, tg = lane & 7;

    if (STATS && tid < 128) { scol[tid] = 0.f; scolq[tid] = 0.f; }
    if (FINAL && tid < 256) { srow[tid] = 0.f; s_w2[tid] = __ldg(&w2[tid]); }

    const int cpsLog = (D == 256) ? 2 : 1;
    const int nkb = nseg << cpsLog;

    const uint32_t xr = (uint32_t)tg << 4;
    const int rowA0 = wm * 32 + tg + (grp & 1) * 8;
    const int rowB0 = wn * 64 + tg + (grp >> 1) * 8;
    const uint32_t kA = (uint32_t)(grp >> 1) * 16;
    const uint32_t kB = (uint32_t)(grp & 1) * 16;

    float acc[2][8][4];
    #pragma unroll
    for (int mt = 0; mt < 2; mt++)
        #pragma unroll
        for (int nt = 0; nt < 8; nt++)
            #pragma unroll
            for (int j = 0; j < 4; j++) acc[mt][nt][j] = 0.f;

    auto load_stage = [&](int kb, int st) {
        int seg = kb >> cpsLog;
        int koff = (kb & ((1 << cpsLog) - 1)) << 6;
        const uint16_t* Aseg = (const uint16_t*)segs.A[seg];
        const uint16_t* Wseg = (const uint16_t*)segs.W[seg];
        uint32_t sA = sb + (uint32_t)st * 32768u;
        uint32_t sB = sA + 16384u;
        #pragma unroll
        for (int t = 0; t < 4; t++) {
            int idx = tid + t * 256;
            int row = idx >> 3, ch = idx & 7;
            uint32_t swz = (uint32_t)row * 128u + (((uint32_t)ch * 16u) ^ (((uint32_t)row & 7u) << 4));
            int grow = bm0 + row;
            int ok = grow < N_NODES;
            const void* gA = Aseg + (size_t)(ok ? grow : 0) * D + koff + ch * 8;
            int sz = ok ? 16 : 0;
            asm volatile("cp.async.cg.shared.global [%0], [%1], 16, %2;"
                         :: "r"(sA + swz), "l"(gA), "r"(sz));
            const void* gB = Wseg + (size_t)(bn0 + row) * D + koff + ch * 8;
            asm volatile("cp.async.cg.shared.global [%0], [%1], 16;"
                         :: "r"(sB + swz), "l"(gB));
        }
        asm volatile("cp.async.commit_group;");
    };

    auto compute_stage = [&](int st) {
        uint32_t aBase = sb + (uint32_t)st * 32768u + (uint32_t)rowA0 * 128u;
        uint32_t bBase = sb + (uint32_t)st * 32768u + 16384u + (uint32_t)rowB0 * 128u;
        #pragma unroll
        for (int kt = 0; kt < 4; kt++) {
            uint32_t a[2][4];
            #pragma unroll
            for (int mt = 0; mt < 2; mt++) {
                uint32_t ad = aBase + (uint32_t)mt * 2048u + (((uint32_t)kt * 32u + kA) ^ xr);
                asm volatile("ldmatrix.sync.aligned.m8n8.x4.shared.b16 {%0,%1,%2,%3}, [%4];"
                    : "=r"(a[mt][0]), "=r"(a[mt][1]), "=r"(a[mt][2]), "=r"(a[mt][3]) : "r"(ad));
            }
            #pragma unroll
            for (int np = 0; np < 4; np++) {
                uint32_t b0, b1, b2r, b3;
                uint32_t bd = bBase + (uint32_t)np * 2048u + (((uint32_t)kt * 32u + kB) ^ xr);
                asm volatile("ldmatrix.sync.aligned.m8n8.x4.shared.b16 {%0,%1,%2,%3}, [%4];"
                    : "=r"(b0), "=r"(b1), "=r"(b2r), "=r"(b3) : "r"(bd));
                #pragma unroll
                for (int mt = 0; mt < 2; mt++) {
                    MMA_F16(acc[mt][np * 2 + 0], a[mt], b0, b1);
                    MMA_F16(acc[mt][np * 2 + 1], a[mt], b2r, b3);
                }
            }
        }
    };

    load_stage(0, 0);
    load_stage(1, 1);
    int st = 0;
    for (int kb = 0; kb < nkb; kb++) {
        if (kb < nkb - 1) asm volatile("cp.async.wait_group 1;");
        else              asm volatile("cp.async.wait_group 0;");
        __syncthreads();
        compute_stage(st);
        if (kb + 2 < nkb) {
            int st2 = st + 2; if (st2 >= 3) st2 -= 3;
            load_stage(kb + 2, st2);
        }
        if (++st == 3) st = 0;
    }

    // ---- epilogue ----
    const int rbase = wm * 32 + (lane >> 2);
    const int cbL = wn * 64 + (lane & 3) * 2;
    float po[8];
    #pragma unroll
    for (int i = 0; i < 8; i++) po[i] = 0.f;

    #pragma unroll
    for (int nt = 0; nt < 8; nt++) {
        int colL = cbL + nt * 8;
        int col = bn0 + colL;
        float bv0 = __ldg(&bias[col]), bv1 = __ldg(&bias[col + 1]);
        float s0 = 0.f, s1 = 0.f, q0 = 0.f, q1 = 0.f;
        #pragma unroll
        for (int mt = 0; mt < 2; mt++) {
            int row = bm0 + rbase + mt * 16;
            float h0 = acc[mt][nt][0] + bv0, h1 = acc[mt][nt][1] + bv1;
            float h2 = acc[mt][nt][2] + bv0, h3 = acc[mt][nt][3] + bv1;
            if (relu) {
                h0 = fmaxf(h0, 0.f); h1 = fmaxf(h1, 0.f);
                h2 = fmaxf(h2, 0.f); h3 = fmaxf(h3, 0.f);
            }
            bool v0 = row < N_NODES, v1 = (row + 8) < N_NODES;
            if (STATS) {
                float a0 = v0 ? h0 : 0.f, a1 = v0 ? h1 : 0.f;
                float a2 = v1 ? h2 : 0.f, a3 = v1 ? h3 : 0.f;
                s0 += a0 + a2; s1 += a1 + a3;
                q0 += a0 * a0 + a2 * a2; q1 += a1 * a1 + a3 * a3;
            }
            if (!FINAL) {
                if (v0) *(float2*)(C + (size_t)row * NT + col) = make_float2(h0, h1);
                if (v1) *(float2*)(C + (size_t)(row + 8) * NT + col) = make_float2(h2, h3);
            } else {
                float w20 = s_w2[colL * 2], w21 = s_w2[colL * 2 + 1];
                float w30 = s_w2[(colL + 1) * 2], w31 = s_w2[(colL + 1) * 2 + 1];
                po[mt * 4 + 0] += h0 * w20 + h1 * w30;
                po[mt * 4 + 1] += h0 * w21 + h1 * w31;
                po[mt * 4 + 2] += h2 * w20 + h3 * w30;
                po[mt * 4 + 3] += h2 * w21 + h3 * w31;
            }
        }
        if (STATS) {
            #pragma unroll
            for (int off = 4; off <= 16; off <<= 1) {
                s0 += __shfl_xor_sync(0xffffffffu, s0, off);
                s1 += __shfl_xor_sync(0xffffffffu, s1, off);
                q0 += __shfl_xor_sync(0xffffffffu, q0, off);
                q1 += __shfl_xor_sync(0xffffffffu, q1, off);
            }
            if ((lane >> 2) == 0) {
                atomicAdd(&scol[colL], s0);  atomicAdd(&scol[colL + 1], s1);
                atomicAdd(&scolq[colL], q0); atomicAdd(&scolq[colL + 1], q1);
            }
        }
    }
    if (STATS) {
        __syncthreads();
        if (tid < 128) {
            atomicAdd(&csum[bn0 + tid], scol[tid]);
            atomicAdd(&cqsum[bn0 + tid], scolq[tid]);
        }
    }
    if (FINAL) {
        #pragma unroll
        for (int mt = 0; mt < 2; mt++) {
            int rl = rbase + mt * 16;
            atomicAdd(&srow[rl * 2 + 0], po[mt * 4 + 0]);
            atomicAdd(&srow[rl * 2 + 1], po[mt * 4 + 1]);
            atomicAdd(&srow[(rl + 8) * 2 + 0], po[mt * 4 + 2]);
            atomicAdd(&srow[(rl + 8) * 2 + 1], po[mt * 4 + 3]);
        }
        __syncthreads();
        if (tid < 128) {
            int grow = bm0 + tid;
            if (grow < N_NODES) {
                C[(size_t)grow * 2 + 0] = srow[tid * 2 + 0] + __ldg(&b2[0]);
                C[(size_t)grow * 2 + 1] = srow[tid * 2 + 1] + __ldg(&b2[1]);
            }
        }
    }
}

// ======== normalize + relu -> fp16 stream (BN affine inline) ========
__global__ void k_normfuse(const float* __restrict__ h,
                           const float* __restrict__ g, const float* __restrict__ be,
                           const float* __restrict__ csum, const float* __restrict__ cqsum,
                           __half* __restrict__ of) {
    __shared__ float sna[HID], snc[HID];
    int tid = threadIdx.x;
    {
        float cs = csum[tid], cq = cqsum[tid];
        float mu  = cs / (float)N_NODES;
        float var = cq / (float)N_NODES - mu * mu;
        var = fmaxf(var, 0.f);
        float a = __ldg(&g[tid]) * rsqrtf(var + EPS);
        sna[tid] = a;
        snc[tid] = __ldg(&be[tid]) - mu * a;
    }
    __syncthreads();
    #pragma unroll
    for (int pass = 0; pass < 4; pass++) {
        int i = blockIdx.x * 1024 + pass * 256 + tid;    // float4 index
        if (i >= N_NODES * HID / 4) return;
        float4 v = ((const float4*)h)[i];
        int cidx = (i * 4) & (HID - 1);
        v.x = fmaxf(v.x * sna[cidx + 0] + snc[cidx + 0], 0.f);
        v.y = fmaxf(v.y * sna[cidx + 1] + snc[cidx + 1], 0.f);
        v.z = fmaxf(v.z * sna[cidx + 2] + snc[cidx + 2], 0.f);
        v.w = fmaxf(v.w * sna[cidx + 3] + snc[cidx + 3], 0.f);
        __half2 f0 = __floats2half2_rn(v.x, v.y);
        __half2 f1 = __floats2half2_rn(v.z, v.w);
        uint2 uf;
        uf.x = *(uint32_t*)&f0; uf.y = *(uint32_t*)&f1;
        ((uint2*)of)[i] = uf;
    }
}

// ======================= launch =======================
extern "C" void kernel_launch(void* const* d_in, const int* in_sizes, int n_in,
                              void* d_out, int out_size) {
    const float* x    = (const float*)d_in[0];
    const int*   ei   = (const int*)d_in[1];   // int32 (JAX x64 disabled)
    const int*   srcv = ei;
    const int*   dstv = ei + N_EDGES;
    const float* wl0 = (const float*)d_in[2];
    const float* wr0 = (const float*)d_in[3];
    const float* b0  = (const float*)d_in[4];
    const float* g0  = (const float*)d_in[5];
    const float* be0 = (const float*)d_in[6];
    const float* wl1 = (const float*)d_in[7];
    const float* wr1 = (const float*)d_in[8];
    const float* b1  = (const float*)d_in[9];
    const float* g1  = (const float*)d_in[10];
    const float* be1 = (const float*)d_in[11];
    const float* wl2 = (const float*)d_in[12];
    const float* wr2 = (const float*)d_in[13];
    const float* b2  = (const float*)d_in[14];
    const float* g2  = (const float*)d_in[15];
    const float* be2 = (const float*)d_in[16];
    const float* cw1 = (const float*)d_in[17];
    const float* cb1 = (const float*)d_in[18];
    const float* cw2 = (const float*)d_in[19];
    const float* cb2 = (const float*)d_in[20];
    float* out = (float*)d_out;

    float* hraw;
    __half *aggf, *xf16, *hf16, *wf;
    float *cs, *cq;
    cudaGetSymbolAddress((void**)&hraw, g_hraw);
    cudaGetSymbolAddress((void**)&aggf, g_aggf);
    cudaGetSymbolAddress((void**)&xf16, g_xf);
    cudaGetSymbolAddress((void**)&hf16, g_hf16);
    cudaGetSymbolAddress((void**)&wf, g_wf);
    cudaGetSymbolAddress((void**)&cs, g_colsum);
    cudaGetSymbolAddress((void**)&cq, g_colsumsq);

    const int SMEM = 3 * 32768;
    cudaFuncSetAttribute(k_mma<256, 1, 0>, cudaFuncAttributeMaxDynamicSharedMemorySize, SMEM);
    cudaFuncSetAttribute(k_mma<128, 0, 1>, cudaFuncAttributeMaxDynamicSharedMemorySize, SMEM);

    // ---- CSR build ----
    k_init<<<(N_NODES + 255) / 256, 256>>>();
    k_hist<<<(N_EDGES + 255) / 256, 256>>>(dstv);
    int nb = (N_NODES + 1023) / 1024;
    k_scan1<<<nb, 1024>>>();
    k_scan2<<<1, 128>>>(nb);
    k_scan3<<<nb, 1024>>>();
    k_fill<<<(N_EDGES + 255) / 256, 256>>>(srcv, dstv);

    // ---- weight + x conversion (fp16 hi/lo) ----
    {
        ConvJobs j;
        j.W[0] = wl0; j.K[0] = 128; j.N[0] = 256; j.oh[0] = WF0LH; j.ol[0] = WF0LL;
        j.W[1] = wr0; j.K[1] = 128; j.N[1] = 256; j.oh[1] = WF0RH; j.ol[1] = WF0RL;
        j.W[2] = wl1; j.K[2] = 256; j.N[2] = 256; j.oh[2] = WF1LH; j.ol[2] = WF1LL;
        j.W[3] = wr1; j.K[3] = 256; j.N[3] = 256; j.oh[3] = WF1RH; j.ol[3] = WF1RL;
        j.W[4] = wl2; j.K[4] = 256; j.N[4] = 256; j.oh[4] = WF2LH; j.ol[4] = WF2LL;
        j.W[5] = wr2; j.K[5] = 256; j.N[5] = 256; j.oh[5] = WF2RH; j.ol[5] = WF2RL;
        j.W[6] = cw1; j.K[6] = 256; j.N[6] = 128; j.oh[6] = CW1H;  j.ol[6] = CW1L;
        k_convall<<<dim3(256, 7), 256>>>(j, wf);
    }
    k_convx<<<(N_NODES * IN_DIM / 4 + 255) / 256, 256>>>(x, xf16);

    int aggGrid = (N_NODES * 32 + 255) / 256;
    int nfGrid  = (N_NODES * HID / 4 + 1023) / 1024;
    int mblocks = (N_NODES + 127) / 128;
    dim3 gMain(2, mblocks);                       // NT=256
    dim3 gCls(1, mblocks);                        // NT=128

    // ---- layer 0 (D=128, 3-seg: agg@wl0_hi + x@wr0(hi,lo)) ----
    k_agg16_128<<<aggGrid, 256>>>(xf16, aggf);
    {
        GemmSegs s;
        s.A[0] = aggf; s.W[0] = wf + WF0LH;
        s.A[1] = xf16; s.W[1] = wf + WF0RH;
        s.A[2] = xf16; s.W[2] = wf + WF0RL;
        s.A[3] = nullptr; s.W[3] = nullptr;
        k_mma<256, 1, 0><<<gMain, 256, SMEM>>>(s, 3, 128, b0, hraw, 0, nullptr, nullptr,
                                               cs + 0 * HID, cq + 0 * HID);
    }
    k_normfuse<<<nfGrid, 256>>>(hraw, g0, be0, cs + 0 * HID, cq + 0 * HID, hf16);

    // ---- layer 1 (D=256, 3-seg: agg@wl1_hi + h@wr1(hi,lo)) ----
    k_agg16_256<<<aggGrid, 256>>>(hf16, aggf);
    {
        GemmSegs s;
        s.A[0] = aggf; s.W[0] = wf + WF1LH;
        s.A[1] = hf16; s.W[1] = wf + WF1RH;
        s.A[2] = hf16; s.W[2] = wf + WF1RL;
        s.A[3] = nullptr; s.W[3] = nullptr;
        k_mma<256, 1, 0><<<gMain, 256, SMEM>>>(s, 3, 256, b1, hraw, 0, nullptr, nullptr,
                                               cs + 1 * HID, cq + 1 * HID);
    }
    k_normfuse<<<nfGrid, 256>>>(hraw, g1, be1, cs + 1 * HID, cq + 1 * HID, hf16);

    // ---- layer 2 (D=256, 3-seg: agg@wl2_hi + h@wr2(hi,lo)) ----
    k_agg16_256<<<aggGrid, 256>>>(hf16, aggf);
    {
        GemmSegs s;
        s.A[0] = aggf; s.W[0] = wf + WF2LH;
        s.A[1] = hf16; s.W[1] = wf + WF2RH;
        s.A[2] = hf16; s.W[2] = wf + WF2RL;
        s.A[3] = nullptr; s.W[3] = nullptr;
        k_mma<256, 1, 0><<<gMain, 256, SMEM>>>(s, 3, 256, b2, hraw, 0, nullptr, nullptr,
                                               cs + 2 * HID, cq + 2 * HID);
    }
    k_normfuse<<<nfGrid, 256>>>(hraw, g2, be2, cs + 2 * HID, cq + 2 * HID, hf16);

    // ---- classifier + head fused (2-seg hi/lo, exact): out = relu(h2@cw1+cb1) @ cw2 + cb2 ----
    {
        GemmSegs s;
        s.A[0] = hf16; s.W[0] = wf + CW1H;
        s.A[1] = hf16; s.W[1] = wf + CW1L;
        s.A[2] = nullptr; s.W[2] = nullptr;
        s.A[3] = nullptr; s.W[3] = nullptr;
        k_mma<128, 0, 1><<<gCls, 256, SMEM>>>(s, 2, 256, cb1, out, 1, cw2, cb2, nullptr, nullptr);
    }
}

// round 11
// speedup vs baseline: 1.9148x; 1.1553x over previous
#include <cuda_runtime.h>
#include <cuda_bf16.h>
#include <cuda_fp16.h>
#include <cstdint>

#define N_NODES 100000
#define N_EDGES 1600000
#define IN_DIM 128
#define HID 256
#define EPS 1e-5f

// ======================= scratch (static __device__) =======================
__device__ float g_hraw[N_NODES * HID];                 // GEMM output fp32
__device__ __half g_aggf[N_NODES * HID];                // fp16 aggregation buffer
__device__ __half g_xf[N_NODES * IN_DIM];               // fp16 x
__device__ __half g_hf16[N_NODES * HID];                // fp16 h_norm stream
__device__ __half g_wf[393216];                         // fp16 weight pool (hi only, W^T [N][K])
__device__ int   g_cnt[N_NODES];
__device__ int   g_cursor[N_NODES];
__device__ int   g_scantmp[N_NODES];
__device__ int   g_rowptr[N_NODES + 1];
__device__ int   g_adj[N_EDGES];
__device__ int   g_bsum[128];
__device__ float g_colsum[3][HID];
__device__ float g_colsumsq[3][HID];

// fp16 pool offsets (elements)
#define WF0L 0
#define WF0R 32768
#define WF1L 65536
#define WF1R 131072
#define WF2L 196608
#define WF2R 262144
#define CW1  327680

__device__ __forceinline__ uint32_t smem_u32(const void* p) {
    uint32_t a;
    asm("{ .reg .u64 t; cvta.to.shared.u64 t, %1; cvt.u32.u64 %0, t; }" : "=r"(a) : "l"(p));
    return a;
}

// ======================= CSR build =======================
__global__ void k_init() {
    int i = blockIdx.x * blockDim.x + threadIdx.x;
    if (i < N_NODES) { g_cnt[i] = 0; g_cursor[i] = 0; }
    if (i < HID) {
        #pragma unroll
        for (int l = 0; l < 3; l++) { g_colsum[l][i] = 0.f; g_colsumsq[l][i] = 0.f; }
    }
}
__global__ void k_hist(const int* __restrict__ dst) {
    int e = blockIdx.x * blockDim.x + threadIdx.x;
    if (e < N_EDGES) atomicAdd(&g_cnt[dst[e]], 1);
}
__global__ void k_scan1() {
    __shared__ int s[1024];
    int i = blockIdx.x * 1024 + threadIdx.x;
    int v = (i < N_NODES) ? g_cnt[i] : 0;
    s[threadIdx.x] = v;
    __syncthreads();
    #pragma unroll
    for (int off = 1; off < 1024; off <<= 1) {
        int t = (threadIdx.x >= off) ? s[threadIdx.x - off] : 0;
        __syncthreads();
        s[threadIdx.x] += t;
        __syncthreads();
    }
    if (i < N_NODES) g_scantmp[i] = s[threadIdx.x];
    if (threadIdx.x == 1023) g_bsum[blockIdx.x] = s[1023];
}
// parallel exclusive scan over nb (<=128) block sums
__global__ void k_scan2(int nb) {
    __shared__ int s[128];
    int t = threadIdx.x;
    int v = (t < nb) ? g_bsum[t] : 0;
    s[t] = v;
    __syncthreads();
    #pragma unroll
    for (int off = 1; off < 128; off <<= 1) {
        int u = (t >= off) ? s[t - off] : 0;
        __syncthreads();
        s[t] += u;
        __syncthreads();
    }
    if (t < nb) g_bsum[t] = s[t] - v;   // exclusive
}
__global__ void k_scan3() {
    int i = blockIdx.x * 1024 + threadIdx.x;
    if (i < N_NODES) {
        g_rowptr[i + 1] = g_scantmp[i] + g_bsum[blockIdx.x];
        if (i == 0) g_rowptr[0] = 0;
    }
}
__global__ void k_fill(const int* __restrict__ src, const int* __restrict__ dst) {
    int e = blockIdx.x * blockDim.x + threadIdx.x;
    if (e < N_EDGES) {
        int d = dst[e];
        int pos = g_rowptr[d] + atomicAdd(&g_cursor[d], 1);
        g_adj[pos] = src[e];
    }
}

// ======================= aggregation =======================
// L0: fp16 x [N,128] gather -> fp16 [N,128]. warp/node, lane = 4 cols, 2-edge unroll.
__global__ void k_agg16_128(const __half* __restrict__ xf, __half* __restrict__ o16) {
    int w = (blockIdx.x * blockDim.x + threadIdx.x) >> 5;
    int lane = threadIdx.x & 31;
    if (w >= N_NODES) return;
    int s0 = g_rowptr[w], s1 = g_rowptr[w + 1];
    float a0 = 0.f, a1 = 0.f, a2 = 0.f, a3 = 0.f;
    int e = s0;
    for (; e + 2 <= s1; e += 2) {
        int na = g_adj[e], nb2 = g_adj[e + 1];
        uint2 va = *(const uint2*)(xf + (size_t)na * IN_DIM + lane * 4);
        uint2 vb = *(const uint2*)(xf + (size_t)nb2 * IN_DIM + lane * 4);
        float2 fa0 = __half22float2(*(const __half2*)&va.x);
        float2 fa1 = __half22float2(*(const __half2*)&va.y);
        float2 fb0 = __half22float2(*(const __half2*)&vb.x);
        float2 fb1 = __half22float2(*(const __half2*)&vb.y);
        a0 += fa0.x + fb0.x; a1 += fa0.y + fb0.y;
        a2 += fa1.x + fb1.x; a3 += fa1.y + fb1.y;
    }
    if (e < s1) {
        uint2 v = *(const uint2*)(xf + (size_t)g_adj[e] * IN_DIM + lane * 4);
        float2 f0 = __half22float2(*(const __half2*)&v.x);
        float2 f1 = __half22float2(*(const __half2*)&v.y);
        a0 += f0.x; a1 += f0.y; a2 += f1.x; a3 += f1.y;
    }
    int deg = s1 - s0;
    float inv = 1.f / (float)(deg > 0 ? deg : 1);
    __half2 h0 = __floats2half2_rn(a0 * inv, a1 * inv);
    __half2 h1 = __floats2half2_rn(a2 * inv, a3 * inv);
    uint2 u;
    u.x = *(uint32_t*)&h0; u.y = *(uint32_t*)&h1;
    *(uint2*)(o16 + (size_t)w * IN_DIM + lane * 4) = u;
}

// L1/L2: fp16 [N,256] gather -> fp16 [N,256]. warp/node, lane = 8 cols, 2-edge unroll.
__global__ void k_agg16_256(const __half* __restrict__ xf, __half* __restrict__ o16) {
    int w = (blockIdx.x * blockDim.x + threadIdx.x) >> 5;
    int lane = threadIdx.x & 31;
    if (w >= N_NODES) return;
    int s0 = g_rowptr[w], s1 = g_rowptr[w + 1];
    float acc[8];
    #pragma unroll
    for (int i = 0; i < 8; i++) acc[i] = 0.f;
    int e = s0;
    for (; e + 2 <= s1; e += 2) {
        size_t ba = (size_t)g_adj[e] * HID + lane * 8;
        size_t bb = (size_t)g_adj[e + 1] * HID + lane * 8;
        uint4 va = *(const uint4*)(xf + ba);
        uint4 vb = *(const uint4*)(xf + bb);
        const uint32_t* pa = &va.x;
        const uint32_t* pb = &vb.x;
        #pragma unroll
        for (int i = 0; i < 4; i++) {
            float2 fa = __half22float2(*(const __half2*)&pa[i]);
            float2 fb = __half22float2(*(const __half2*)&pb[i]);
            acc[i * 2 + 0] += fa.x + fb.x;
            acc[i * 2 + 1] += fa.y + fb.y;
        }
    }
    if (e < s1) {
        size_t base = (size_t)g_adj[e] * HID + lane * 8;
        uint4 v = *(const uint4*)(xf + base);
        const uint32_t* p = &v.x;
        #pragma unroll
        for (int i = 0; i < 4; i++) {
            float2 f = __half22float2(*(const __half2*)&p[i]);
            acc[i * 2 + 0] += f.x;
            acc[i * 2 + 1] += f.y;
        }
    }
    int deg = s1 - s0;
    float inv = 1.f / (float)(deg > 0 ? deg : 1);
    uint4 u;
    uint32_t* p = &u.x;
    #pragma unroll
    for (int i = 0; i < 4; i++) {
        __half2 h = __floats2half2_rn(acc[i * 2] * inv, acc[i * 2 + 1] * inv);
        p[i] = *(uint32_t*)&h;
    }
    *(uint4*)(o16 + (size_t)w * HID + lane * 8) = u;
}

// ======================= conversions =======================
__global__ void k_convx(const float* __restrict__ x, __half* __restrict__ o16) {
    int i = blockIdx.x * blockDim.x + threadIdx.x;   // float4 index
    if (i >= N_NODES * IN_DIM / 4) return;
    float4 v = ((const float4*)x)[i];
    __half2 f0 = __floats2half2_rn(v.x, v.y);
    __half2 f1 = __floats2half2_rn(v.z, v.w);
    uint2 uf;
    uf.x = *(uint32_t*)&f0; uf.y = *(uint32_t*)&f1;
    ((uint2*)o16)[i] = uf;
}

// weights: fp32 [K,N] -> W^T fp16 [N][K] (hi only)
struct ConvJobs { const float* W[7]; int K[7]; int N[7]; int off[7]; };
__global__ void k_convall(ConvJobs j, __half* __restrict__ wf) {
    int s = blockIdx.y;
    int K = j.K[s], N = j.N[s];
    int id = blockIdx.x * blockDim.x + threadIdx.x;
    if (id >= K * N) return;
    int k = id / N, n = id % N;
    float v = __ldg(&j.W[s][id]);
    wf[j.off[s] + (size_t)n * K + k] = __float2half_rn(v);
}

// ======================= f16 mma.sync GEMM =======================
// 256 threads, 8 warps 4x2, warp tile 32x64, BM=128, BN=128, BK=64, 3-stage.
struct GemmSegs { const void* A[2]; const void* W[2]; };

#define MMA_F16(c, a, b0v, b1v) \
    asm volatile("mma.sync.aligned.m16n8k16.row.col.f32.f16.f16.f32 " \
        "{%0,%1,%2,%3}, {%4,%5,%6,%7}, {%8,%9}, {%0,%1,%2,%3};" \
        : "+f"((c)[0]), "+f"((c)[1]), "+f"((c)[2]), "+f"((c)[3]) \
        : "r"((a)[0]), "r"((a)[1]), "r"((a)[2]), "r"((a)[3]), "r"(b0v), "r"(b1v))

template <int NT, int STATS, int FINAL>
__global__ __launch_bounds__(256, 2)
void k_mma(GemmSegs segs, int nseg, int D, const float* __restrict__ bias,
           float* __restrict__ C, int relu,
           const float* __restrict__ w2, const float* __restrict__ b2,
           float* __restrict__ csum, float* __restrict__ cqsum) {
    extern __shared__ char dsm[];                 // 3 stages x [A 16KB | B 16KB]
    __shared__ float scol[128], scolq[128];
    __shared__ float srow[256];
    __shared__ float s_w2[256];
    const uint32_t sb = smem_u32(dsm);
    const int tid = threadIdx.x;
    const int lane = tid & 31, wid = tid >> 5;
    const int wm = wid & 3, wn = wid >> 2;        // 4 m-warps x 2 n-warps
    const int bm0 = blockIdx.y * 128, bn0 = blockIdx.x * 128;
    const int grp = lane >> 3, tg = lane & 7;

    if (STATS && tid < 128) { scol[tid] = 0.f; scolq[tid] = 0.f; }
    if (FINAL && tid < 256) { srow[tid] = 0.f; s_w2[tid] = __ldg(&w2[tid]); }

    const int cpsLog = (D == 256) ? 2 : 1;
    const int nkb = nseg << cpsLog;

    const uint32_t xr = (uint32_t)tg << 4;
    const int rowA0 = wm * 32 + tg + (grp & 1) * 8;
    const int rowB0 = wn * 64 + tg + (grp >> 1) * 8;
    const uint32_t kA = (uint32_t)(grp >> 1) * 16;
    const uint32_t kB = (uint32_t)(grp & 1) * 16;

    float acc[2][8][4];
    #pragma unroll
    for (int mt = 0; mt < 2; mt++)
        #pragma unroll
        for (int nt = 0; nt < 8; nt++)
            #pragma unroll
            for (int j = 0; j < 4; j++) acc[mt][nt][j] = 0.f;

    auto load_stage = [&](int kb, int st) {
        int seg = kb >> cpsLog;
        int koff = (kb & ((1 << cpsLog) - 1)) << 6;
        const uint16_t* Aseg = (const uint16_t*)segs.A[seg];
        const uint16_t* Wseg = (const uint16_t*)segs.W[seg];
        uint32_t sA = sb + (uint32_t)st * 32768u;
        uint32_t sB = sA + 16384u;
        #pragma unroll
        for (int t = 0; t < 4; t++) {
            int idx = tid + t * 256;
            int row = idx >> 3, ch = idx & 7;
            uint32_t swz = (uint32_t)row * 128u + (((uint32_t)ch * 16u) ^ (((uint32_t)row & 7u) << 4));
            int grow = bm0 + row;
            int ok = grow < N_NODES;
            const void* gA = Aseg + (size_t)(ok ? grow : 0) * D + koff + ch * 8;
            int sz = ok ? 16 : 0;
            asm volatile("cp.async.cg.shared.global [%0], [%1], 16, %2;"
                         :: "r"(sA + swz), "l"(gA), "r"(sz));
            const void* gB = Wseg + (size_t)(bn0 + row) * D + koff + ch * 8;
            asm volatile("cp.async.cg.shared.global [%0], [%1], 16;"
                         :: "r"(sB + swz), "l"(gB));
        }
        asm volatile("cp.async.commit_group;");
    };

    auto compute_stage = [&](int st) {
        uint32_t aBase = sb + (uint32_t)st * 32768u + (uint32_t)rowA0 * 128u;
        uint32_t bBase = sb + (uint32_t)st * 32768u + 16384u + (uint32_t)rowB0 * 128u;
        #pragma unroll
        for (int kt = 0; kt < 4; kt++) {
            uint32_t a[2][4];
            #pragma unroll
            for (int mt = 0; mt < 2; mt++) {
                uint32_t ad = aBase + (uint32_t)mt * 2048u + (((uint32_t)kt * 32u + kA) ^ xr);
                asm volatile("ldmatrix.sync.aligned.m8n8.x4.shared.b16 {%0,%1,%2,%3}, [%4];"
                    : "=r"(a[mt][0]), "=r"(a[mt][1]), "=r"(a[mt][2]), "=r"(a[mt][3]) : "r"(ad));
            }
            #pragma unroll
            for (int np = 0; np < 4; np++) {
                uint32_t b0, b1, b2r, b3;
                uint32_t bd = bBase + (uint32_t)np * 2048u + (((uint32_t)kt * 32u + kB) ^ xr);
                asm volatile("ldmatrix.sync.aligned.m8n8.x4.shared.b16 {%0,%1,%2,%3}, [%4];"
                    : "=r"(b0), "=r"(b1), "=r"(b2r), "=r"(b3) : "r"(bd));
                #pragma unroll
                for (int mt = 0; mt < 2; mt++) {
                    MMA_F16(acc[mt][np * 2 + 0], a[mt], b0, b1);
                    MMA_F16(acc[mt][np * 2 + 1], a[mt], b2r, b3);
                }
            }
        }
    };

    load_stage(0, 0);
    if (nkb > 1) load_stage(1, 1);
    int st = 0;
    for (int kb = 0; kb < nkb; kb++) {
        if (kb < nkb - 1) asm volatile("cp.async.wait_group 1;");
        else              asm volatile("cp.async.wait_group 0;");
        __syncthreads();
        compute_stage(st);
        if (kb + 2 < nkb) {
            int st2 = st + 2; if (st2 >= 3) st2 -= 3;
            load_stage(kb + 2, st2);
        }
        if (++st == 3) st = 0;
    }

    // ---- epilogue ----
    const int rbase = wm * 32 + (lane >> 2);
    const int cbL = wn * 64 + (lane & 3) * 2;
    float po[8];
    #pragma unroll
    for (int i = 0; i < 8; i++) po[i] = 0.f;

    #pragma unroll
    for (int nt = 0; nt < 8; nt++) {
        int colL = cbL + nt * 8;
        int col = bn0 + colL;
        float bv0 = __ldg(&bias[col]), bv1 = __ldg(&bias[col + 1]);
        float s0 = 0.f, s1 = 0.f, q0 = 0.f, q1 = 0.f;
        #pragma unroll
        for (int mt = 0; mt < 2; mt++) {
            int row = bm0 + rbase + mt * 16;
            float h0 = acc[mt][nt][0] + bv0, h1 = acc[mt][nt][1] + bv1;
            float h2 = acc[mt][nt][2] + bv0, h3 = acc[mt][nt][3] + bv1;
            if (relu) {
                h0 = fmaxf(h0, 0.f); h1 = fmaxf(h1, 0.f);
                h2 = fmaxf(h2, 0.f); h3 = fmaxf(h3, 0.f);
            }
            bool v0 = row < N_NODES, v1 = (row + 8) < N_NODES;
            if (STATS) {
                float a0 = v0 ? h0 : 0.f, a1 = v0 ? h1 : 0.f;
                float a2 = v1 ? h2 : 0.f, a3 = v1 ? h3 : 0.f;
                s0 += a0 + a2; s1 += a1 + a3;
                q0 += a0 * a0 + a2 * a2; q1 += a1 * a1 + a3 * a3;
            }
            if (!FINAL) {
                if (v0) *(float2*)(C + (size_t)row * NT + col) = make_float2(h0, h1);
                if (v1) *(float2*)(C + (size_t)(row + 8) * NT + col) = make_float2(h2, h3);
            } else {
                float w20 = s_w2[colL * 2], w21 = s_w2[colL * 2 + 1];
                float w30 = s_w2[(colL + 1) * 2], w31 = s_w2[(colL + 1) * 2 + 1];
                po[mt * 4 + 0] += h0 * w20 + h1 * w30;
                po[mt * 4 + 1] += h0 * w21 + h1 * w31;
                po[mt * 4 + 2] += h2 * w20 + h3 * w30;
                po[mt * 4 + 3] += h2 * w21 + h3 * w31;
            }
        }
        if (STATS) {
            #pragma unroll
            for (int off = 4; off <= 16; off <<= 1) {
                s0 += __shfl_xor_sync(0xffffffffu, s0, off);
                s1 += __shfl_xor_sync(0xffffffffu, s1, off);
                q0 += __shfl_xor_sync(0xffffffffu, q0, off);
                q1 += __shfl_xor_sync(0xffffffffu, q1, off);
            }
            if ((lane >> 2) == 0) {
                atomicAdd(&scol[colL], s0);  atomicAdd(&scol[colL + 1], s1);
                atomicAdd(&scolq[colL], q0); atomicAdd(&scolq[colL + 1], q1);
            }
        }
    }
    if (STATS) {
        __syncthreads();
        if (tid < 128) {
            atomicAdd(&csum[bn0 + tid], scol[tid]);
            atomicAdd(&cqsum[bn0 + tid], scolq[tid]);
        }
    }
    if (FINAL) {
        #pragma unroll
        for (int mt = 0; mt < 2; mt++) {
            int rl = rbase + mt * 16;
            atomicAdd(&srow[rl * 2 + 0], po[mt * 4 + 0]);
            atomicAdd(&srow[rl * 2 + 1], po[mt * 4 + 1]);
            atomicAdd(&srow[(rl + 8) * 2 + 0], po[mt * 4 + 2]);
            atomicAdd(&srow[(rl + 8) * 2 + 1], po[mt * 4 + 3]);
        }
        __syncthreads();
        if (tid < 128) {
            int grow = bm0 + tid;
            if (grow < N_NODES) {
                C[(size_t)grow * 2 + 0] = srow[tid * 2 + 0] + __ldg(&b2[0]);
                C[(size_t)grow * 2 + 1] = srow[tid * 2 + 1] + __ldg(&b2[1]);
            }
        }
    }
}

// ======== normalize + relu -> fp16 stream (BN affine inline) ========
__global__ void k_normfuse(const float* __restrict__ h,
                           const float* __restrict__ g, const float* __restrict__ be,
                           const float* __restrict__ csum, const float* __restrict__ cqsum,
                           __half* __restrict__ of) {
    __shared__ float sna[HID], snc[HID];
    int tid = threadIdx.x;
    {
        float cs = csum[tid], cq = cqsum[tid];
        float mu  = cs / (float)N_NODES;
        float var = cq / (float)N_NODES - mu * mu;
        var = fmaxf(var, 0.f);
        float a = __ldg(&g[tid]) * rsqrtf(var + EPS);
        sna[tid] = a;
        snc[tid] = __ldg(&be[tid]) - mu * a;
    }
    __syncthreads();
    #pragma unroll
    for (int pass = 0; pass < 4; pass++) {
        int i = blockIdx.x * 1024 + pass * 256 + tid;    // float4 index
        if (i >= N_NODES * HID / 4) return;
        float4 v = ((const float4*)h)[i];
        int cidx = (i * 4) & (HID - 1);
        v.x = fmaxf(v.x * sna[cidx + 0] + snc[cidx + 0], 0.f);
        v.y = fmaxf(v.y * sna[cidx + 1] + snc[cidx + 1], 0.f);
        v.z = fmaxf(v.z * sna[cidx + 2] + snc[cidx + 2], 0.f);
        v.w = fmaxf(v.w * sna[cidx + 3] + snc[cidx + 3], 0.f);
        __half2 f0 = __floats2half2_rn(v.x, v.y);
        __half2 f1 = __floats2half2_rn(v.z, v.w);
        uint2 uf;
        uf.x = *(uint32_t*)&f0; uf.y = *(uint32_t*)&f1;
        ((uint2*)of)[i] = uf;
    }
}

// ======================= launch =======================
extern "C" void kernel_launch(void* const* d_in, const int* in_sizes, int n_in,
                              void* d_out, int out_size) {
    const float* x    = (const float*)d_in[0];
    const int*   ei   = (const int*)d_in[1];   // int32 (JAX x64 disabled)
    const int*   srcv = ei;
    const int*   dstv = ei + N_EDGES;
    const float* wl0 = (const float*)d_in[2];
    const float* wr0 = (const float*)d_in[3];
    const float* b0  = (const float*)d_in[4];
    const float* g0  = (const float*)d_in[5];
    const float* be0 = (const float*)d_in[6];
    const float* wl1 = (const float*)d_in[7];
    const float* wr1 = (const float*)d_in[8];
    const float* b1  = (const float*)d_in[9];
    const float* g1  = (const float*)d_in[10];
    const float* be1 = (const float*)d_in[11];
    const float* wl2 = (const float*)d_in[12];
    const float* wr2 = (const float*)d_in[13];
    const float* b2  = (const float*)d_in[14];
    const float* g2  = (const float*)d_in[15];
    const float* be2 = (const float*)d_in[16];
    const float* cw1 = (const float*)d_in[17];
    const float* cb1 = (const float*)d_in[18];
    const float* cw2 = (const float*)d_in[19];
    const float* cb2 = (const float*)d_in[20];
    float* out = (float*)d_out;

    float* hraw;
    __half *aggf, *xf16, *hf16, *wf;
    float *cs, *cq;
    cudaGetSymbolAddress((void**)&hraw, g_hraw);
    cudaGetSymbolAddress((void**)&aggf, g_aggf);
    cudaGetSymbolAddress((void**)&xf16, g_xf);
    cudaGetSymbolAddress((void**)&hf16, g_hf16);
    cudaGetSymbolAddress((void**)&wf, g_wf);
    cudaGetSymbolAddress((void**)&cs, g_colsum);
    cudaGetSymbolAddress((void**)&cq, g_colsumsq);

    const int SMEM = 3 * 32768;
    cudaFuncSetAttribute(k_mma<256, 1, 0>, cudaFuncAttributeMaxDynamicSharedMemorySize, SMEM);
    cudaFuncSetAttribute(k_mma<128, 0, 1>, cudaFuncAttributeMaxDynamicSharedMemorySize, SMEM);

    // ---- CSR build ----
    k_init<<<(N_NODES + 255) / 256, 256>>>();
    k_hist<<<(N_EDGES + 255) / 256, 256>>>(dstv);
    int nb = (N_NODES + 1023) / 1024;
    k_scan1<<<nb, 1024>>>();
    k_scan2<<<1, 128>>>(nb);
    k_scan3<<<nb, 1024>>>();
    k_fill<<<(N_EDGES + 255) / 256, 256>>>(srcv, dstv);

    // ---- weight + x conversion (fp16 hi only) ----
    {
        ConvJobs j;
        j.W[0] = wl0; j.K[0] = 128; j.N[0] = 256; j.off[0] = WF0L;
        j.W[1] = wr0; j.K[1] = 128; j.N[1] = 256; j.off[1] = WF0R;
        j.W[2] = wl1; j.K[2] = 256; j.N[2] = 256; j.off[2] = WF1L;
        j.W[3] = wr1; j.K[3] = 256; j.N[3] = 256; j.off[3] = WF1R;
        j.W[4] = wl2; j.K[4] = 256; j.N[4] = 256; j.off[4] = WF2L;
        j.W[5] = wr2; j.K[5] = 256; j.N[5] = 256; j.off[5] = WF2R;
        j.W[6] = cw1; j.K[6] = 256; j.N[6] = 128; j.off[6] = CW1;
        k_convall<<<dim3(256, 7), 256>>>(j, wf);
    }
    k_convx<<<(N_NODES * IN_DIM / 4 + 255) / 256, 256>>>(x, xf16);

    int aggGrid = (N_NODES * 32 + 255) / 256;
    int nfGrid  = (N_NODES * HID / 4 + 1023) / 1024;
    int mblocks = (N_NODES + 127) / 128;
    dim3 gMain(2, mblocks);                       // NT=256
    dim3 gCls(1, mblocks);                        // NT=128

    // ---- layer 0 (D=128, 2-seg: agg@wl0 + x@wr0) ----
    k_agg16_128<<<aggGrid, 256>>>(xf16, aggf);
    {
        GemmSegs s;
        s.A[0] = aggf; s.W[0] = wf + WF0L;
        s.A[1] = xf16; s.W[1] = wf + WF0R;
        k_mma<256, 1, 0><<<gMain, 256, SMEM>>>(s, 2, 128, b0, hraw, 0, nullptr, nullptr,
                                               cs + 0 * HID, cq + 0 * HID);
    }
    k_normfuse<<<nfGrid, 256>>>(hraw, g0, be0, cs + 0 * HID, cq + 0 * HID, hf16);

    // ---- layer 1 (D=256, 2-seg) ----
    k_agg16_256<<<aggGrid, 256>>>(hf16, aggf);
    {
        GemmSegs s;
        s.A[0] = aggf; s.W[0] = wf + WF1L;
        s.A[1] = hf16; s.W[1] = wf + WF1R;
        k_mma<256, 1, 0><<<gMain, 256, SMEM>>>(s, 2, 256, b1, hraw, 0, nullptr, nullptr,
                                               cs + 1 * HID, cq + 1 * HID);
    }
    k_normfuse<<<nfGrid, 256>>>(hraw, g1, be1, cs + 1 * HID, cq + 1 * HID, hf16);

    // ---- layer 2 (D=256, 2-seg) ----
    k_agg16_256<<<aggGrid, 256>>>(hf16, aggf);
    {
        GemmSegs s;
        s.A[0] = aggf; s.W[0] = wf + WF2L;
        s.A[1] = hf16; s.W[1] = wf + WF2R;
        k_mma<256, 1, 0><<<gMain, 256, SMEM>>>(s, 2, 256, b2, hraw, 0, nullptr, nullptr,
                                               cs + 2 * HID, cq + 2 * HID);
    }
    k_normfuse<<<nfGrid, 256>>>(hraw, g2, be2, cs + 2 * HID, cq + 2 * HID, hf16);

    // ---- classifier + head fused (1-seg): out = relu(h2@cw1+cb1) @ cw2 + cb2 ----
    {
        GemmSegs s;
        s.A[0] = hf16; s.W[0] = wf + CW1;
        s.A[1] = nullptr; s.W[1] = nullptr;
        k_mma<128, 0, 1><<<gCls, 256, SMEM>>>(s, 1, 256, cb1, out, 1, cw2, cb2, nullptr, nullptr);
    }
}

// round 12
// speedup vs baseline: 2.0989x; 1.0961x over previous
#include <cuda_runtime.h>
#include <cuda_bf16.h>
#include <cuda_fp16.h>
#include <cstdint>

#define N_NODES 100000
#define N_EDGES 1600000
#define IN_DIM 128
#define HID 256
#define EPS 1e-5f

// ======================= scratch (static __device__) =======================
__device__ __half g_hpre[N_NODES * HID];                // pre-BN h (fp16)
__device__ __half g_aggf[N_NODES * HID];                // fp16 aggregation buffer
__device__ __half g_xf[N_NODES * IN_DIM];               // fp16 x
__device__ __half g_hf16[N_NODES * HID];                // fp16 h_norm stream
__device__ __half g_wf[393216];                         // fp16 weight pool (W^T [N][K])
__device__ int   g_cnt[N_NODES];
__device__ int   g_cursor[N_NODES];
__device__ int   g_scantmp[N_NODES];
__device__ int   g_rowptr[N_NODES + 1];
__device__ int   g_adj[N_EDGES];
__device__ int   g_bsum[128];
__device__ float g_colsum[3][HID];
__device__ float g_colsumsq[3][HID];

// fp16 pool offsets (elements)
#define WF0L 0
#define WF0R 32768
#define WF1L 65536
#define WF1R 131072
#define WF2L 196608
#define WF2R 262144
#define CW1  327680

__device__ __forceinline__ uint32_t smem_u32(const void* p) {
    uint32_t a;
    asm("{ .reg .u64 t; cvta.to.shared.u64 t, %1; cvt.u32.u64 %0, t; }" : "=r"(a) : "l"(p));
    return a;
}

// ======================= CSR build =======================
__global__ void k_init() {
    int i = blockIdx.x * blockDim.x + threadIdx.x;
    if (i < N_NODES) { g_cnt[i] = 0; g_cursor[i] = 0; }
    if (i < HID) {
        #pragma unroll
        for (int l = 0; l < 3; l++) { g_colsum[l][i] = 0.f; g_colsumsq[l][i] = 0.f; }
    }
}

// ===== mega kernel: hist + weight conversion + x conversion (independent jobs) =====
struct ConvJobs { const float* W[7]; int K[7]; int N[7]; int off[7]; };

__global__ void k_mega(const int* __restrict__ dst, ConvJobs j, __half* __restrict__ wf,
                       const float* __restrict__ x, __half* __restrict__ o16,
                       int histB, int convB) {
    int b = blockIdx.x;
    if (b < histB) {
        int e = b * 256 + threadIdx.x;
        if (e < N_EDGES) atomicAdd(&g_cnt[dst[e]], 1);
    } else if (b < histB + convB) {
        int bb = b - histB;
        int s = bb >> 8;                       // job index (256 blocks per job)
        int id = (bb & 255) * 256 + threadIdx.x;
        int K = j.K[s], N = j.N[s];
        if (id < K * N) {
            int k = id / N, n = id % N;
            float v = __ldg(&j.W[s][id]);
            wf[j.off[s] + (size_t)n * K + k] = __float2half_rn(v);
        }
    } else {
        int i = (b - histB - convB) * 256 + threadIdx.x;   // float4 index
        if (i < N_NODES * IN_DIM / 4) {
            float4 v = ((const float4*)x)[i];
            __half2 f0 = __floats2half2_rn(v.x, v.y);
            __half2 f1 = __floats2half2_rn(v.z, v.w);
            uint2 uf;
            uf.x = *(uint32_t*)&f0; uf.y = *(uint32_t*)&f1;
            ((uint2*)o16)[i] = uf;
        }
    }
}

__global__ void k_scan1() {
    __shared__ int s[1024];
    int i = blockIdx.x * 1024 + threadIdx.x;
    int v = (i < N_NODES) ? g_cnt[i] : 0;
    s[threadIdx.x] = v;
    __syncthreads();
    #pragma unroll
    for (int off = 1; off < 1024; off <<= 1) {
        int t = (threadIdx.x >= off) ? s[threadIdx.x - off] : 0;
        __syncthreads();
        s[threadIdx.x] += t;
        __syncthreads();
    }
    if (i < N_NODES) g_scantmp[i] = s[threadIdx.x];
    if (threadIdx.x == 1023) g_bsum[blockIdx.x] = s[1023];
}
__global__ void k_scan2(int nb) {
    __shared__ int s[128];
    int t = threadIdx.x;
    int v = (t < nb) ? g_bsum[t] : 0;
    s[t] = v;
    __syncthreads();
    #pragma unroll
    for (int off = 1; off < 128; off <<= 1) {
        int u = (t >= off) ? s[t - off] : 0;
        __syncthreads();
        s[t] += u;
        __syncthreads();
    }
    if (t < nb) g_bsum[t] = s[t] - v;   // exclusive
}
__global__ void k_scan3() {
    int i = blockIdx.x * 1024 + threadIdx.x;
    if (i < N_NODES) {
        g_rowptr[i + 1] = g_scantmp[i] + g_bsum[blockIdx.x];
        if (i == 0) g_rowptr[0] = 0;
    }
}
__global__ void k_fill(const int* __restrict__ src, const int* __restrict__ dst) {
    int e = blockIdx.x * blockDim.x + threadIdx.x;
    if (e < N_EDGES) {
        int d = dst[e];
        int pos = g_rowptr[d] + atomicAdd(&g_cursor[d], 1);
        g_adj[pos] = src[e];
    }
}

// ======================= aggregation =======================
__global__ void k_agg16_128(const __half* __restrict__ xf, __half* __restrict__ o16) {
    int w = (blockIdx.x * blockDim.x + threadIdx.x) >> 5;
    int lane = threadIdx.x & 31;
    if (w >= N_NODES) return;
    int s0 = g_rowptr[w], s1 = g_rowptr[w + 1];
    float a0 = 0.f, a1 = 0.f, a2 = 0.f, a3 = 0.f;
    int e = s0;
    for (; e + 2 <= s1; e += 2) {
        int na = g_adj[e], nb2 = g_adj[e + 1];
        uint2 va = *(const uint2*)(xf + (size_t)na * IN_DIM + lane * 4);
        uint2 vb = *(const uint2*)(xf + (size_t)nb2 * IN_DIM + lane * 4);
        float2 fa0 = __half22float2(*(const __half2*)&va.x);
        float2 fa1 = __half22float2(*(const __half2*)&va.y);
        float2 fb0 = __half22float2(*(const __half2*)&vb.x);
        float2 fb1 = __half22float2(*(const __half2*)&vb.y);
        a0 += fa0.x + fb0.x; a1 += fa0.y + fb0.y;
        a2 += fa1.x + fb1.x; a3 += fa1.y + fb1.y;
    }
    if (e < s1) {
        uint2 v = *(const uint2*)(xf + (size_t)g_adj[e] * IN_DIM + lane * 4);
        float2 f0 = __half22float2(*(const __half2*)&v.x);
        float2 f1 = __half22float2(*(const __half2*)&v.y);
        a0 += f0.x; a1 += f0.y; a2 += f1.x; a3 += f1.y;
    }
    int deg = s1 - s0;
    float inv = 1.f / (float)(deg > 0 ? deg : 1);
    __half2 h0 = __floats2half2_rn(a0 * inv, a1 * inv);
    __half2 h1 = __floats2half2_rn(a2 * inv, a3 * inv);
    uint2 u;
    u.x = *(uint32_t*)&h0; u.y = *(uint32_t*)&h1;
    *(uint2*)(o16 + (size_t)w * IN_DIM + lane * 4) = u;
}

__global__ void k_agg16_256(const __half* __restrict__ xf, __half* __restrict__ o16) {
    int w = (blockIdx.x * blockDim.x + threadIdx.x) >> 5;
    int lane = threadIdx.x & 31;
    if (w >= N_NODES) return;
    int s0 = g_rowptr[w], s1 = g_rowptr[w + 1];
    float acc[8];
    #pragma unroll
    for (int i = 0; i < 8; i++) acc[i] = 0.f;
    int e = s0;
    for (; e + 2 <= s1; e += 2) {
        size_t ba = (size_t)g_adj[e] * HID + lane * 8;
        size_t bb = (size_t)g_adj[e + 1] * HID + lane * 8;
        uint4 va = *(const uint4*)(xf + ba);
        uint4 vb = *(const uint4*)(xf + bb);
        const uint32_t* pa = &va.x;
        const uint32_t* pb = &vb.x;
        #pragma unroll
        for (int i = 0; i < 4; i++) {
            float2 fa = __half22float2(*(const __half2*)&pa[i]);
            float2 fb = __half22float2(*(const __half2*)&pb[i]);
            acc[i * 2 + 0] += fa.x + fb.x;
            acc[i * 2 + 1] += fa.y + fb.y;
        }
    }
    if (e < s1) {
        size_t base = (size_t)g_adj[e] * HID + lane * 8;
        uint4 v = *(const uint4*)(xf + base);
        const uint32_t* p = &v.x;
        #pragma unroll
        for (int i = 0; i < 4; i++) {
            float2 f = __half22float2(*(const __half2*)&p[i]);
            acc[i * 2 + 0] += f.x;
            acc[i * 2 + 1] += f.y;
        }
    }
    int deg = s1 - s0;
    float inv = 1.f / (float)(deg > 0 ? deg : 1);
    uint4 u;
    uint32_t* p = &u.x;
    #pragma unroll
    for (int i = 0; i < 4; i++) {
        __half2 h = __floats2half2_rn(acc[i * 2] * inv, acc[i * 2 + 1] * inv);
        p[i] = *(uint32_t*)&h;
    }
    *(uint4*)(o16 + (size_t)w * HID + lane * 8) = u;
}

// ======================= f16 mma.sync GEMM =======================
// 256 threads, 8 warps 4x2, warp tile 32x64, BM=128, BN=128, BK=64, 3-stage.
// !FINAL: C = __half* pre-BN h (fp16); stats accumulated in fp32.
// FINAL:  C = float* out[N,2]; fused out = relu(z) @ w2 + b2.
struct GemmSegs { const void* A[2]; const void* W[2]; };

#define MMA_F16(c, a, b0v, b1v) \
    asm volatile("mma.sync.aligned.m16n8k16.row.col.f32.f16.f16.f32 " \
        "{%0,%1,%2,%3}, {%4,%5,%6,%7}, {%8,%9}, {%0,%1,%2,%3};" \
        : "+f"((c)[0]), "+f"((c)[1]), "+f"((c)[2]), "+f"((c)[3]) \
        : "r"((a)[0]), "r"((a)[1]), "r"((a)[2]), "r"((a)[3]), "r"(b0v), "r"(b1v))

template <int NT, int STATS, int FINAL>
__global__ __launch_bounds__(256, 2)
void k_mma(GemmSegs segs, int nseg, int D, const float* __restrict__ bias,
           void* __restrict__ Cv, int relu,
           const float* __restrict__ w2, const float* __restrict__ b2,
           float* __restrict__ csum, float* __restrict__ cqsum) {
    extern __shared__ char dsm[];                 // 3 stages x [A 16KB | B 16KB]
    __shared__ float scol[128], scolq[128];
    __shared__ float srow[256];
    __shared__ float s_w2[256];
    const uint32_t sb = smem_u32(dsm);
    const int tid = threadIdx.x;
    const int lane = tid & 31, wid = tid >> 5;
    const int wm = wid & 3, wn = wid >> 2;        // 4 m-warps x 2 n-warps
    const int bm0 = blockIdx.y * 128, bn0 = blockIdx.x * 128;
    const int grp = lane >> 3, tg = lane & 7;

    if (STATS && tid < 128) { scol[tid] = 0.f; scolq[tid] = 0.f; }
    if (FINAL && tid < 256) { srow[tid] = 0.f; s_w2[tid] = __ldg(&w2[tid]); }

    const int cpsLog = (D == 256) ? 2 : 1;
    const int nkb = nseg << cpsLog;

    const uint32_t xr = (uint32_t)tg << 4;
    const int rowA0 = wm * 32 + tg + (grp & 1) * 8;
    const int rowB0 = wn * 64 + tg + (grp >> 1) * 8;
    const uint32_t kA = (uint32_t)(grp >> 1) * 16;
    const uint32_t kB = (uint32_t)(grp & 1) * 16;

    float acc[2][8][4];
    #pragma unroll
    for (int mt = 0; mt < 2; mt++)
        #pragma unroll
        for (int nt = 0; nt < 8; nt++)
            #pragma unroll
            for (int j = 0; j < 4; j++) acc[mt][nt][j] = 0.f;

    auto load_stage = [&](int kb, int st) {
        int seg = kb >> cpsLog;
        int koff = (kb & ((1 << cpsLog) - 1)) << 6;
        const uint16_t* Aseg = (const uint16_t*)segs.A[seg];
        const uint16_t* Wseg = (const uint16_t*)segs.W[seg];
        uint32_t sA = sb + (uint32_t)st * 32768u;
        uint32_t sB = sA + 16384u;
        #pragma unroll
        for (int t = 0; t < 4; t++) {
            int idx = tid + t * 256;
            int row = idx >> 3, ch = idx & 7;
            uint32_t swz = (uint32_t)row * 128u + (((uint32_t)ch * 16u) ^ (((uint32_t)row & 7u) << 4));
            int grow = bm0 + row;
            int ok = grow < N_NODES;
            const void* gA = Aseg + (size_t)(ok ? grow : 0) * D + koff + ch * 8;
            int sz = ok ? 16 : 0;
            asm volatile("cp.async.cg.shared.global [%0], [%1], 16, %2;"
                         :: "r"(sA + swz), "l"(gA), "r"(sz));
            const void* gB = Wseg + (size_t)(bn0 + row) * D + koff + ch * 8;
            asm volatile("cp.async.cg.shared.global [%0], [%1], 16;"
                         :: "r"(sB + swz), "l"(gB));
        }
        asm volatile("cp.async.commit_group;");
    };

    auto compute_stage = [&](int st) {
        uint32_t aBase = sb + (uint32_t)st * 32768u + (uint32_t)rowA0 * 128u;
        uint32_t bBase = sb + (uint32_t)st * 32768u + 16384u + (uint32_t)rowB0 * 128u;
        #pragma unroll
        for (int kt = 0; kt < 4; kt++) {
            uint32_t a[2][4];
            #pragma unroll
            for (int mt = 0; mt < 2; mt++) {
                uint32_t ad = aBase + (uint32_t)mt * 2048u + (((uint32_t)kt * 32u + kA) ^ xr);
                asm volatile("ldmatrix.sync.aligned.m8n8.x4.shared.b16 {%0,%1,%2,%3}, [%4];"
                    : "=r"(a[mt][0]), "=r"(a[mt][1]), "=r"(a[mt][2]), "=r"(a[mt][3]) : "r"(ad));
            }
            #pragma unroll
            for (int np = 0; np < 4; np++) {
                uint32_t b0, b1, b2r, b3;
                uint32_t bd = bBase + (uint32_t)np * 2048u + (((uint32_t)kt * 32u + kB) ^ xr);
                asm volatile("ldmatrix.sync.aligned.m8n8.x4.shared.b16 {%0,%1,%2,%3}, [%4];"
                    : "=r"(b0), "=r"(b1), "=r"(b2r), "=r"(b3) : "r"(bd));
                #pragma unroll
                for (int mt = 0; mt < 2; mt++) {
                    MMA_F16(acc[mt][np * 2 + 0], a[mt], b0, b1);
                    MMA_F16(acc[mt][np * 2 + 1], a[mt], b2r, b3);
                }
            }
        }
    };

    load_stage(0, 0);
    if (nkb > 1) load_stage(1, 1);
    int st = 0;
    for (int kb = 0; kb < nkb; kb++) {
        if (kb < nkb - 1) asm volatile("cp.async.wait_group 1;");
        else              asm volatile("cp.async.wait_group 0;");
        __syncthreads();
        compute_stage(st);
        if (kb + 2 < nkb) {
            int st2 = st + 2; if (st2 >= 3) st2 -= 3;
            load_stage(kb + 2, st2);
        }
        if (++st == 3) st = 0;
    }

    // ---- epilogue ----
    const int rbase = wm * 32 + (lane >> 2);
    const int cbL = wn * 64 + (lane & 3) * 2;
    float po[8];
    #pragma unroll
    for (int i = 0; i < 8; i++) po[i] = 0.f;
    __half* C16 = (__half*)Cv;
    float* Cf = (float*)Cv;

    #pragma unroll
    for (int nt = 0; nt < 8; nt++) {
        int colL = cbL + nt * 8;
        int col = bn0 + colL;
        float bv0 = __ldg(&bias[col]), bv1 = __ldg(&bias[col + 1]);
        float s0 = 0.f, s1 = 0.f, q0 = 0.f, q1 = 0.f;
        #pragma unroll
        for (int mt = 0; mt < 2; mt++) {
            int row = bm0 + rbase + mt * 16;
            float h0 = acc[mt][nt][0] + bv0, h1 = acc[mt][nt][1] + bv1;
            float h2 = acc[mt][nt][2] + bv0, h3 = acc[mt][nt][3] + bv1;
            if (relu) {
                h0 = fmaxf(h0, 0.f); h1 = fmaxf(h1, 0.f);
                h2 = fmaxf(h2, 0.f); h3 = fmaxf(h3, 0.f);
            }
            bool v0 = row < N_NODES, v1 = (row + 8) < N_NODES;
            if (STATS) {
                float a0 = v0 ? h0 : 0.f, a1 = v0 ? h1 : 0.f;
                float a2 = v1 ? h2 : 0.f, a3 = v1 ? h3 : 0.f;
                s0 += a0 + a2; s1 += a1 + a3;
                q0 += a0 * a0 + a2 * a2; q1 += a1 * a1 + a3 * a3;
            }
            if (!FINAL) {
                if (v0) {
                    __half2 p = __floats2half2_rn(h0, h1);
                    *(uint32_t*)(C16 + (size_t)row * NT + col) = *(uint32_t*)&p;
                }
                if (v1) {
                    __half2 p = __floats2half2_rn(h2, h3);
                    *(uint32_t*)(C16 + (size_t)(row + 8) * NT + col) = *(uint32_t*)&p;
                }
            } else {
                float w20 = s_w2[colL * 2], w21 = s_w2[colL * 2 + 1];
                float w30 = s_w2[(colL + 1) * 2], w31 = s_w2[(colL + 1) * 2 + 1];
                po[mt * 4 + 0] += h0 * w20 + h1 * w30;
                po[mt * 4 + 1] += h0 * w21 + h1 * w31;
                po[mt * 4 + 2] += h2 * w20 + h3 * w30;
                po[mt * 4 + 3] += h2 * w21 + h3 * w31;
            }
        }
        if (STATS) {
            #pragma unroll
            for (int off = 4; off <= 16; off <<= 1) {
                s0 += __shfl_xor_sync(0xffffffffu, s0, off);
                s1 += __shfl_xor_sync(0xffffffffu, s1, off);
                q0 += __shfl_xor_sync(0xffffffffu, q0, off);
                q1 += __shfl_xor_sync(0xffffffffu, q1, off);
            }
            if ((lane >> 2) == 0) {
                atomicAdd(&scol[colL], s0);  atomicAdd(&scol[colL + 1], s1);
                atomicAdd(&scolq[colL], q0); atomicAdd(&scolq[colL + 1], q1);
            }
        }
    }
    if (STATS) {
        __syncthreads();
        if (tid < 128) {
            atomicAdd(&csum[bn0 + tid], scol[tid]);
            atomicAdd(&cqsum[bn0 + tid], scolq[tid]);
        }
    }
    if (FINAL) {
        #pragma unroll
        for (int mt = 0; mt < 2; mt++) {
            int rl = rbase + mt * 16;
            atomicAdd(&srow[rl * 2 + 0], po[mt * 4 + 0]);
            atomicAdd(&srow[rl * 2 + 1], po[mt * 4 + 1]);
            atomicAdd(&srow[(rl + 8) * 2 + 0], po[mt * 4 + 2]);
            atomicAdd(&srow[(rl + 8) * 2 + 1], po[mt * 4 + 3]);
        }
        __syncthreads();
        if (tid < 128) {
            int grow = bm0 + tid;
            if (grow < N_NODES) {
                Cf[(size_t)grow * 2 + 0] = srow[tid * 2 + 0] + __ldg(&b2[0]);
                Cf[(size_t)grow * 2 + 1] = srow[tid * 2 + 1] + __ldg(&b2[1]);
            }
        }
    }
}

// ======== normalize + relu: fp16 pre-BN h -> fp16 stream (BN affine inline) ========
__global__ void k_normfuse(const __half* __restrict__ h,
                           const float* __restrict__ g, const float* __restrict__ be,
                           const float* __restrict__ csum, const float* __restrict__ cqsum,
                           __half* __restrict__ of) {
    __shared__ float sna[HID], snc[HID];
    int tid = threadIdx.x;
    {
        float cs = csum[tid], cq = cqsum[tid];
        float mu  = cs / (float)N_NODES;
        float var = cq / (float)N_NODES - mu * mu;
        var = fmaxf(var, 0.f);
        float a = __ldg(&g[tid]) * rsqrtf(var + EPS);
        sna[tid] = a;
        snc[tid] = __ldg(&be[tid]) - mu * a;
    }
    __syncthreads();
    #pragma unroll
    for (int pass = 0; pass < 4; pass++) {
        int i = blockIdx.x * 1024 + pass * 256 + tid;    // 4-half group index
        if (i >= N_NODES * HID / 4) return;
        uint2 v = ((const uint2*)h)[i];
        float2 f01 = __half22float2(*(const __half2*)&v.x);
        float2 f23 = __half22float2(*(const __half2*)&v.y);
        int cidx = (i * 4) & (HID - 1);
        f01.x = fmaxf(f01.x * sna[cidx + 0] + snc[cidx + 0], 0.f);
        f01.y = fmaxf(f01.y * sna[cidx + 1] + snc[cidx + 1], 0.f);
        f23.x = fmaxf(f23.x * sna[cidx + 2] + snc[cidx + 2], 0.f);
        f23.y = fmaxf(f23.y * sna[cidx + 3] + snc[cidx + 3], 0.f);
        __half2 o0 = __floats2half2_rn(f01.x, f01.y);
        __half2 o1 = __floats2half2_rn(f23.x, f23.y);
        uint2 uf;
        uf.x = *(uint32_t*)&o0; uf.y = *(uint32_t*)&o1;
        ((uint2*)of)[i] = uf;
    }
}

// ======================= launch =======================
extern "C" void kernel_launch(void* const* d_in, const int* in_sizes, int n_in,
                              void* d_out, int out_size) {
    const float* x    = (const float*)d_in[0];
    const int*   ei   = (const int*)d_in[1];   // int32 (JAX x64 disabled)
    const int*   srcv = ei;
    const int*   dstv = ei + N_EDGES;
    const float* wl0 = (const float*)d_in[2];
    const float* wr0 = (const float*)d_in[3];
    const float* b0  = (const float*)d_in[4];
    const float* g0  = (const float*)d_in[5];
    const float* be0 = (const float*)d_in[6];
    const float* wl1 = (const float*)d_in[7];
    const float* wr1 = (const float*)d_in[8];
    const float* b1  = (const float*)d_in[9];
    const float* g1  = (const float*)d_in[10];
    const float* be1 = (const float*)d_in[11];
    const float* wl2 = (const float*)d_in[12];
    const float* wr2 = (const float*)d_in[13];
    const float* b2  = (const float*)d_in[14];
    const float* g2  = (const float*)d_in[15];
    const float* be2 = (const float*)d_in[16];
    const float* cw1 = (const float*)d_in[17];
    const float* cb1 = (const float*)d_in[18];
    const float* cw2 = (const float*)d_in[19];
    const float* cb2 = (const float*)d_in[20];
    float* out = (float*)d_out;

    __half *hpre, *aggf, *xf16, *hf16, *wf;
    float *cs, *cq;
    cudaGetSymbolAddress((void**)&hpre, g_hpre);
    cudaGetSymbolAddress((void**)&aggf, g_aggf);
    cudaGetSymbolAddress((void**)&xf16, g_xf);
    cudaGetSymbolAddress((void**)&hf16, g_hf16);
    cudaGetSymbolAddress((void**)&wf, g_wf);
    cudaGetSymbolAddress((void**)&cs, g_colsum);
    cudaGetSymbolAddress((void**)&cq, g_colsumsq);

    const int SMEM = 3 * 32768;
    cudaFuncSetAttribute(k_mma<256, 1, 0>, cudaFuncAttributeMaxDynamicSharedMemorySize, SMEM);
    cudaFuncSetAttribute(k_mma<128, 0, 1>, cudaFuncAttributeMaxDynamicSharedMemorySize, SMEM);

    // ---- init, then mega (hist + weight conv + x conv, all independent) ----
    k_init<<<(N_NODES + 255) / 256, 256>>>();
    {
        ConvJobs j;
        j.W[0] = wl0; j.K[0] = 128; j.N[0] = 256; j.off[0] = WF0L;
        j.W[1] = wr0; j.K[1] = 128; j.N[1] = 256; j.off[1] = WF0R;
        j.W[2] = wl1; j.K[2] = 256; j.N[2] = 256; j.off[2] = WF1L;
        j.W[3] = wr1; j.K[3] = 256; j.N[3] = 256; j.off[3] = WF1R;
        j.W[4] = wl2; j.K[4] = 256; j.N[4] = 256; j.off[4] = WF2L;
        j.W[5] = wr2; j.K[5] = 256; j.N[5] = 256; j.off[5] = WF2R;
        j.W[6] = cw1; j.K[6] = 256; j.N[6] = 128; j.off[6] = CW1;
        int histB = (N_EDGES + 255) / 256;            // 6250
        int convB = 7 * 256;                          // 1792
        int convxB = (N_NODES * IN_DIM / 4 + 255) / 256;   // 12500
        k_mega<<<histB + convB + convxB, 256>>>(dstv, j, wf, x, xf16, histB, convB);
    }
    int nb = (N_NODES + 1023) / 1024;
    k_scan1<<<nb, 1024>>>();
    k_scan2<<<1, 128>>>(nb);
    k_scan3<<<nb, 1024>>>();
    k_fill<<<(N_EDGES + 255) / 256, 256>>>(srcv, dstv);

    int aggGrid = (N_NODES * 32 + 255) / 256;
    int nfGrid  = (N_NODES * HID / 4 + 1023) / 1024;
    int mblocks = (N_NODES + 127) / 128;
    dim3 gMain(2, mblocks);                       // NT=256
    dim3 gCls(1, mblocks);                        // NT=128

    // ---- layer 0 (D=128, 2-seg: agg@wl0 + x@wr0) ----
    k_agg16_128<<<aggGrid, 256>>>(xf16, aggf);
    {
        GemmSegs s;
        s.A[0] = aggf; s.W[0] = wf + WF0L;
        s.A[1] = xf16; s.W[1] = wf + WF0R;
        k_mma<256, 1, 0><<<gMain, 256, SMEM>>>(s, 2, 128, b0, hpre, 0, nullptr, nullptr,
                                               cs + 0 * HID, cq + 0 * HID);
    }
    k_normfuse<<<nfGrid, 256>>>(hpre, g0, be0, cs + 0 * HID, cq + 0 * HID, hf16);

    // ---- layer 1 (D=256, 2-seg) ----
    k_agg16_256<<<aggGrid, 256>>>(hf16, aggf);
    {
        GemmSegs s;
        s.A[0] = aggf; s.W[0] = wf + WF1L;
        s.A[1] = hf16; s.W[1] = wf + WF1R;
        k_mma<256, 1, 0><<<gMain, 256, SMEM>>>(s, 2, 256, b1, hpre, 0, nullptr, nullptr,
                                               cs + 1 * HID, cq + 1 * HID);
    }
    k_normfuse<<<nfGrid, 256>>>(hpre, g1, be1, cs + 1 * HID, cq + 1 * HID, hf16);

    // ---- layer 2 (D=256, 2-seg) ----
    k_agg16_256<<<aggGrid, 256>>>(hf16, aggf);
    {
        GemmSegs s;
        s.A[0] = aggf; s.W[0] = wf + WF2L;
        s.A[1] = hf16; s.W[1] = wf + WF2R;
        k_mma<256, 1, 0><<<gMain, 256, SMEM>>>(s, 2, 256, b2, hpre, 0, nullptr, nullptr,
                                               cs + 2 * HID, cq + 2 * HID);
    }
    k_normfuse<<<nfGrid, 256>>>(hpre, g2, be2, cs + 2 * HID, cq + 2 * HID, hf16);

    // ---- classifier + head fused (1-seg): out = relu(h2@cw1+cb1) @ cw2 + cb2 ----
    {
        GemmSegs s;
        s.A[0] = hf16; s.W[0] = wf + CW1;
        s.A[1] = nullptr; s.W[1] = nullptr;
        k_mma<128, 0, 1><<<gCls, 256, SMEM>>>(s, 1, 256, cb1, out, 1, cw2, cb2, nullptr, nullptr);
    }
}